// round 3
// baseline (speedup 1.0000x reference)
#include <cuda_runtime.h>
#include <math.h>

// Problem constants (fixed by setup_inputs)
#define B_  64
#define Q_  1000
#define BQ  64000        // B_*Q_
#define D_  256

// sigmoid(x) > 0.7  <=>  x > ln(0.7/0.3)
#define LOGIT_THR 0.8472978603872034f

// ---------------------------------------------------------------------------
// Device-global scratch (allocation-free per harness rules)
// ---------------------------------------------------------------------------
__device__ float         g_h[BQ * D_];     // ping buffer: hdd, then m1
__device__ float         g_a[BQ * D_];     // pong buffer: ary_feat
__device__ float         g_delta[BQ * 4];
__device__ float         g_score[BQ];
__device__ unsigned char g_flags[BQ];      // bit0 left_fold, bit1 right_fold, bit2 left_ary, bit3 right_ary
__device__ unsigned char g_cand[BQ];       // bit0 left cand, bit1 right cand

// ---------------------------------------------------------------------------
// Kernel 1: per-query class-logit threshold flags (sigmoid folded into thr)
// ---------------------------------------------------------------------------
__global__ void k_flags(const float* __restrict__ logits)
{
    int q = blockIdx.x * blockDim.x + threadIdx.x;
    if (q >= BQ) return;
    const float* l = logits + (long)q * 6;
    unsigned f = 0;
    if (l[0] > LOGIT_THR) f |= 1u;   // left_fold  (VF_L = 0)
    if (l[4] > LOGIT_THR) f |= 2u;   // right_fold (VF_R = 4)
    if (l[1] > LOGIT_THR) f |= 4u;   // left_ary   (ARY_L = 1)
    if (l[5] > LOGIT_THR) f |= 8u;   // right_ary  (ARY_R = 5)
    g_flags[q] = (unsigned char)f;
}

// ---------------------------------------------------------------------------
// Kernel 2: per-batch candidate mask via IoU against compacted arytenoid set
// ---------------------------------------------------------------------------
__global__ void __launch_bounds__(1024) k_mask(const float* __restrict__ boxes)
{
    __shared__ float tx1[Q_], ty1[Q_], tx2[Q_], ty2[Q_], tar[Q_];
    __shared__ unsigned char tfl[Q_];
    __shared__ int cnt;

    int b = blockIdx.x;
    int t = threadIdx.x;
    if (t == 0) cnt = 0;
    __syncthreads();

    float x1 = 0.f, y1 = 0.f, x2 = 0.f, y2 = 0.f, ar = 0.f;
    unsigned f = 0;
    if (t < Q_) {
        const float* bx = boxes + ((long)b * Q_ + t) * 4;
        float cx = bx[0], cy = bx[1], w = bx[2], h = bx[3];
        x1 = cx - w * 0.5f; y1 = cy - h * 0.5f;
        x2 = cx + w * 0.5f; y2 = cy + h * 0.5f;
        ar = w * h;
        f = g_flags[(long)b * Q_ + t];
        if (f & 0xCu) {                       // any arytenoid flag
            int p = atomicAdd(&cnt, 1);
            tx1[p] = x1; ty1[p] = y1; tx2[p] = x2; ty2[p] = y2; tar[p] = ar;
            tfl[p] = (unsigned char)((f >> 2) & 3u);  // bit0 left_ary, bit1 right_ary
        }
    }
    __syncthreads();

    if (t < Q_) {
        int n = cnt;
        unsigned has = 0;
        for (int j = 0; j < n; j++) {
            float xl = fmaxf(x1, tx1[j]);
            float yt = fmaxf(y1, ty1[j]);
            float xr = fminf(x2, tx2[j]);
            float yb = fminf(y2, ty2[j]);
            float iw = fmaxf(xr - xl, 0.f);
            float ih = fmaxf(yb - yt, 0.f);
            float inter = iw * ih;
            float uni = ar + tar[j] - inter;
            if (inter / uni > 0.5f) {
                has |= (unsigned)tfl[j];
                if (has == 3u) break;
            }
        }
        unsigned cm = 0;
        if ((f & 1u) && !(has & 1u)) cm |= 1u;   // left_fold & ~has_left
        if ((f & 2u) && !(has & 2u)) cm |= 2u;   // right_fold & ~has_right
        g_cand[(long)b * Q_ + t] = (unsigned char)cm;
    }
}

// ---------------------------------------------------------------------------
// GEMM:  C[64000,256] = epilogue( A[64000,256] @ W[256,256] + bias )
// Block tile 64x256 (full row width), BK=32, 256 threads, 8x8 per-thread tile.
// EPI: 0 = LayerNorm+ReLU -> store
//      1 = store + fused score = row . W_s + b_s
//      2 = ReLU -> store
//      3 = ReLU -> fused delta = row @ W_b3 + b_b3 (no store)
// SRC/DST: 0 = g_h, 1 = g_a, 2 = external/none
// ---------------------------------------------------------------------------
#define EPI_LNRELU 0
#define EPI_SCORE  1
#define EPI_RELU   2
#define EPI_DELTA  3
#define GBM 64
#define GBK 32

template<int EPI, int SRC, int DST>
__global__ void __launch_bounds__(256, 2) k_gemm(
    const float* __restrict__ Aext,
    const float* __restrict__ W,
    const float* __restrict__ bias,
    const float* __restrict__ aux_w,   // W_s [256] or W_b3 [256,4]
    const float* __restrict__ aux_b,   // b_s [1]  or b_b3 [4]
    const float* __restrict__ lng,
    const float* __restrict__ lnb)
{
    __shared__ float As[GBM][GBK];    // 8 KB
    __shared__ float Ws[GBK][D_];     // 32 KB

    const float* A = (SRC == 0) ? g_h : (SRC == 1) ? g_a : Aext;

    int tid = threadIdx.x;
    int blockRow = blockIdx.x * GBM;

    float acc[8][8];
#pragma unroll
    for (int i = 0; i < 8; i++)
#pragma unroll
        for (int j = 0; j < 8; j++) acc[i][j] = 0.f;

    int arow = tid >> 3;          // 0..31
    int aseg = tid & 7;           // 0..7  -> k offset aseg*4
    int wrow = tid >> 3;          // 0..31 (k row)
    int wc   = tid & 7;           // base float4 col

    const float* Ap = A + (long)(blockRow + arow) * D_;
    const int rb = (tid >> 5) * 8;
    const int tx = tid & 31;
    const int c0 = tx * 4;
    const int c1 = 128 + tx * 4;

    for (int k0 = 0; k0 < D_; k0 += GBK) {
        float4 a0 = *(const float4*)(Ap + k0 + aseg * 4);
        float4 a1 = *(const float4*)(Ap + 32 * D_ + k0 + aseg * 4);
        *(float4*)&As[arow][aseg * 4]      = a0;
        *(float4*)&As[arow + 32][aseg * 4] = a1;

        const float* Wp = W + (long)(k0 + wrow) * D_;
#pragma unroll
        for (int s = 0; s < 8; s++) {
            float4 wv = *(const float4*)(Wp + (wc + s * 8) * 4);
            *(float4*)&Ws[wrow][(wc + s * 8) * 4] = wv;
        }
        __syncthreads();

#pragma unroll
        for (int k = 0; k < GBK; k++) {
            float4 b0 = *(const float4*)&Ws[k][c0];
            float4 b1 = *(const float4*)&Ws[k][c1];
#pragma unroll
            for (int i = 0; i < 8; i++) {
                float a = As[rb + i][k];
                acc[i][0] += a * b0.x; acc[i][1] += a * b0.y;
                acc[i][2] += a * b0.z; acc[i][3] += a * b0.w;
                acc[i][4] += a * b1.x; acc[i][5] += a * b1.y;
                acc[i][6] += a * b1.z; acc[i][7] += a * b1.w;
            }
        }
        __syncthreads();
    }

    // ---------------- epilogue ----------------
    float bb[8];
#pragma unroll
    for (int j = 0; j < 4; j++) { bb[j] = bias[c0 + j]; bb[4 + j] = bias[c1 + j]; }

    float gg[8], gb2[8];
    if (EPI == EPI_LNRELU) {
#pragma unroll
        for (int j = 0; j < 4; j++) {
            gg[j] = lng[c0 + j]; gg[4 + j] = lng[c1 + j];
            gb2[j] = lnb[c0 + j]; gb2[4 + j] = lnb[c1 + j];
        }
    }
    float ws[8];
    if (EPI == EPI_SCORE) {
#pragma unroll
        for (int j = 0; j < 4; j++) { ws[j] = aux_w[c0 + j]; ws[4 + j] = aux_w[c1 + j]; }
    }
    float wd[8][4];
    if (EPI == EPI_DELTA) {
#pragma unroll
        for (int j = 0; j < 4; j++) {
            float4 v0 = *(const float4*)(aux_w + (c0 + j) * 4);
            float4 v1 = *(const float4*)(aux_w + (c1 + j) * 4);
            wd[j][0] = v0.x; wd[j][1] = v0.y; wd[j][2] = v0.z; wd[j][3] = v0.w;
            wd[4 + j][0] = v1.x; wd[4 + j][1] = v1.y; wd[4 + j][2] = v1.z; wd[4 + j][3] = v1.w;
        }
    }

    float* Cp = (DST == 0) ? g_h : (DST == 1) ? g_a : (float*)0;

#pragma unroll
    for (int i = 0; i < 8; i++) {
        int gr = blockRow + rb + i;
        float v[8];
#pragma unroll
        for (int j = 0; j < 8; j++) v[j] = acc[i][j] + bb[j];

        if (EPI == EPI_LNRELU) {
            float s = 0.f, s2 = 0.f;
#pragma unroll
            for (int j = 0; j < 8; j++) { s += v[j]; s2 += v[j] * v[j]; }
#pragma unroll
            for (int off = 16; off > 0; off >>= 1) {
                s  += __shfl_xor_sync(0xffffffffu, s,  off);
                s2 += __shfl_xor_sync(0xffffffffu, s2, off);
            }
            float mu = s * (1.f / 256.f);
            float var = s2 * (1.f / 256.f) - mu * mu;
            float rstd = rsqrtf(var + 1e-5f);
#pragma unroll
            for (int j = 0; j < 8; j++)
                v[j] = fmaxf((v[j] - mu) * rstd * gg[j] + gb2[j], 0.f);
        }
        if (EPI == EPI_RELU || EPI == EPI_DELTA) {
#pragma unroll
            for (int j = 0; j < 8; j++) v[j] = fmaxf(v[j], 0.f);
        }

        if (EPI != EPI_DELTA) {
            float* o = Cp + (long)gr * D_;
            float4 o0 = make_float4(v[0], v[1], v[2], v[3]);
            float4 o1 = make_float4(v[4], v[5], v[6], v[7]);
            *(float4*)(o + c0) = o0;
            *(float4*)(o + c1) = o1;
        }

        if (EPI == EPI_SCORE) {
            float p = 0.f;
#pragma unroll
            for (int j = 0; j < 8; j++) p += v[j] * ws[j];
#pragma unroll
            for (int off = 16; off > 0; off >>= 1)
                p += __shfl_xor_sync(0xffffffffu, p, off);
            if (tx == 0) g_score[gr] = p + aux_b[0];
        }
        if (EPI == EPI_DELTA) {
            float p[4] = {0.f, 0.f, 0.f, 0.f};
#pragma unroll
            for (int j = 0; j < 8; j++) {
                p[0] += v[j] * wd[j][0];
                p[1] += v[j] * wd[j][1];
                p[2] += v[j] * wd[j][2];
                p[3] += v[j] * wd[j][3];
            }
#pragma unroll
            for (int c = 0; c < 4; c++) {
#pragma unroll
                for (int off = 16; off > 0; off >>= 1)
                    p[c] += __shfl_xor_sync(0xffffffffu, p[c], off);
            }
            if (tx == 0) {
                g_delta[(long)gr * 4 + 0] = p[0] + aux_b[0];
                g_delta[(long)gr * 4 + 1] = p[1] + aux_b[1];
                g_delta[(long)gr * 4 + 2] = p[2] + aux_b[2];
                g_delta[(long)gr * 4 + 3] = p[3] + aux_b[3];
            }
        }
    }
}

// ---------------------------------------------------------------------------
// Kernel: final assembly — candidate boxes, inverse sigmoid, refine, mask, pack
// Output layout: out[B,Q,2,5] flattened (640000 floats), then cand_mask[B,Q,2]
// as 0/1 floats (128000) if out_size covers it.
// ---------------------------------------------------------------------------
__global__ void k_finalize(const float* __restrict__ boxes,
                           float* __restrict__ out, int out_size)
{
    int q = blockIdx.x * blockDim.x + threadIdx.x;
    if (q >= BQ) return;

    float4 bx = *(const float4*)(boxes + (long)q * 4);
    float cx = bx.x, cy = bx.y, w = bx.z, h = bx.w;
    float ny = cy + 0.5f * h;
    float nw = w * 0.8f;
    float nh = h * 0.8f;

    float dd[4];
    dd[0] = g_delta[(long)q * 4 + 0];
    dd[1] = g_delta[(long)q * 4 + 1];
    dd[2] = g_delta[(long)q * 4 + 2];
    dd[3] = g_delta[(long)q * 4 + 3];
    float sc = g_score[q];
    unsigned cm = g_cand[q];

    float lb[4]  = {cx,             ny, nw, nh};
    float rbx[4] = {cx + 0.1f * w,  ny, nw, nh};

#pragma unroll
    for (int s = 0; s < 2; s++) {
        float m = ((cm >> s) & 1u) ? 1.f : 0.f;
        const float* cb = s ? rbx : lb;
        long base = ((long)q * 2 + s) * 5;
#pragma unroll
        for (int c = 0; c < 4; c++) {
            float x = cb[c];
            x = fminf(fmaxf(x, 0.f), 1.f);
            float num = fmaxf(x, 1e-5f);
            float den = fmaxf(1.f - x, 1e-5f);
            float inv = logf(num / den);
            float t = dd[c] + inv;
            float r = 1.f / (1.f + expf(-t));
            out[base + c] = r * m;
        }
        out[base + 4] = sc * m;
        if (out_size >= BQ * 10 + BQ * 2)
            out[BQ * 10 + (long)q * 2 + s] = m;
    }
}

// ---------------------------------------------------------------------------
// Launch
// ---------------------------------------------------------------------------
extern "C" void kernel_launch(void* const* d_in, const int* in_sizes, int n_in,
                              void* d_out, int out_size)
{
    const float* logits   = (const float*)d_in[0];
    const float* boxes    = (const float*)d_in[1];
    const float* features = (const float*)d_in[2];
    // d_in[3] = memory: unused by the reference computation
    const float* W_p1 = (const float*)d_in[4];
    const float* b_p1 = (const float*)d_in[5];
    const float* ln_g = (const float*)d_in[6];
    const float* ln_b = (const float*)d_in[7];
    const float* W_p2 = (const float*)d_in[8];
    const float* b_p2 = (const float*)d_in[9];
    const float* W_b1 = (const float*)d_in[10];
    const float* b_b1 = (const float*)d_in[11];
    const float* W_b2 = (const float*)d_in[12];
    const float* b_b2 = (const float*)d_in[13];
    const float* W_b3 = (const float*)d_in[14];
    const float* b_b3 = (const float*)d_in[15];
    const float* W_s  = (const float*)d_in[16];
    const float* b_s  = (const float*)d_in[17];
    float* out = (float*)d_out;

    (void)in_sizes; (void)n_in;

    k_flags<<<(BQ + 255) / 256, 256>>>(logits);
    k_mask<<<B_, 1024>>>(boxes);

    // hdd = relu(LN(features @ W_p1 + b_p1))           -> g_h
    k_gemm<EPI_LNRELU, 2, 0><<<1000, 256>>>(features, W_p1, b_p1,
                                            nullptr, nullptr, ln_g, ln_b);
    // ary_feat = g_h @ W_p2 + b_p2 -> g_a ; score = ary_feat . W_s + b_s
    k_gemm<EPI_SCORE, 0, 1><<<1000, 256>>>(nullptr, W_p2, b_p2,
                                           W_s, b_s, nullptr, nullptr);
    // m1 = relu(g_a @ W_b1 + b_b1)                     -> g_h
    k_gemm<EPI_RELU, 1, 0><<<1000, 256>>>(nullptr, W_b1, b_b1,
                                          nullptr, nullptr, nullptr, nullptr);
    // m2 = relu(g_h @ W_b2 + b_b2); delta = m2 @ W_b3 + b_b3 (m2 never stored)
    k_gemm<EPI_DELTA, 0, 2><<<1000, 256>>>(nullptr, W_b2, b_b2,
                                           W_b3, b_b3, nullptr, nullptr);

    k_finalize<<<(BQ + 255) / 256, 256>>>(boxes, out, out_size);
}

// round 9
// speedup vs baseline: 1.2407x; 1.2407x over previous
#include <cuda_runtime.h>
#include <cuda_bf16.h>
#include <math.h>
#include <stdint.h>

// Problem constants
#define B_  64
#define Q_  1000
#define BQ  64000
#define D_  256
#define LOGIT_THR 0.8472978603872034f   // sigmoid(x)>0.7  <=>  x>ln(7/3)

// ---------------------------------------------------------------------------
// Device-global scratch. Activations/weights stored as SEPARATE hi/lo bf16
// planes so cp.async can stream them into smem without unpacking.
// x = hi + lo (both bf16), dropping lo*lo in products (rel err ~2^-16).
// ---------------------------------------------------------------------------
__device__ __nv_bfloat16 g_xH[2][BQ * D_];    // 32 MB each
__device__ __nv_bfloat16 g_xL[2][BQ * D_];
__device__ __nv_bfloat16 g_wHp[4][D_ * D_];   // transposed weights [n][k]
__device__ __nv_bfloat16 g_wLp[4][D_ * D_];
__device__ float         g_delta[BQ * 4];
__device__ float         g_score[BQ];
__device__ unsigned char g_flags[BQ];
__device__ unsigned char g_cand[BQ];

// ---------------------------------------------------------------------------
// PTX helpers (all plain-sm_100 legal: cp.async / ldmatrix / mma.sync)
// ---------------------------------------------------------------------------
__device__ __forceinline__ uint32_t smem_u32(const void* p) {
    uint32_t r;
    asm("{ .reg .u64 t; cvta.to.shared.u64 t, %1; cvt.u32.u64 %0, t; }" : "=r"(r) : "l"(p));
    return r;
}
__device__ __forceinline__ void cp16(uint32_t dst, const void* src) {
    asm volatile("cp.async.cg.shared.global [%0], [%1], 16;" :: "r"(dst), "l"(src));
}
#define CP_COMMIT()  asm volatile("cp.async.commit_group;")
#define CP_WAIT1()   asm volatile("cp.async.wait_group 1;")
#define CP_WAIT0()   asm volatile("cp.async.wait_group 0;")

#define LDSM4(r, addr) \
    asm volatile("ldmatrix.sync.aligned.m8n8.x4.shared.b16 {%0,%1,%2,%3}, [%4];" \
        : "=r"((r)[0]), "=r"((r)[1]), "=r"((r)[2]), "=r"((r)[3]) : "r"(addr))

#define MMA(d, a, b0, b1) \
    asm volatile("mma.sync.aligned.m16n8k16.row.col.f32.bf16.bf16.f32 " \
        "{%0,%1,%2,%3},{%4,%5,%6,%7},{%8,%9},{%0,%1,%2,%3};" \
        : "+f"((d)[0]), "+f"((d)[1]), "+f"((d)[2]), "+f"((d)[3]) \
        : "r"((a)[0]), "r"((a)[1]), "r"((a)[2]), "r"((a)[3]), "r"(b0), "r"(b1))

__device__ __forceinline__ uint32_t pack2(float a, float b) {
    return (uint32_t)__bfloat16_as_ushort(__float2bfloat16(a))
         | ((uint32_t)__bfloat16_as_ushort(__float2bfloat16(b)) << 16);
}

// ---------------------------------------------------------------------------
// Small kernels: flags / mask / converts / finalize
// ---------------------------------------------------------------------------
__global__ void k_flags(const float* __restrict__ logits)
{
    int q = blockIdx.x * blockDim.x + threadIdx.x;
    if (q >= BQ) return;
    const float* l = logits + (long)q * 6;
    unsigned f = 0;
    if (l[0] > LOGIT_THR) f |= 1u;
    if (l[4] > LOGIT_THR) f |= 2u;
    if (l[1] > LOGIT_THR) f |= 4u;
    if (l[5] > LOGIT_THR) f |= 8u;
    g_flags[q] = (unsigned char)f;
}

__global__ void __launch_bounds__(1024) k_mask(const float* __restrict__ boxes)
{
    __shared__ float tx1[Q_], ty1[Q_], tx2[Q_], ty2[Q_], tar[Q_];
    __shared__ unsigned char tfl[Q_];
    __shared__ int cnt;
    int b = blockIdx.x, t = threadIdx.x;
    if (t == 0) cnt = 0;
    __syncthreads();
    float x1 = 0.f, y1 = 0.f, x2 = 0.f, y2 = 0.f, ar = 0.f;
    unsigned f = 0;
    if (t < Q_) {
        const float* bx = boxes + ((long)b * Q_ + t) * 4;
        float cx = bx[0], cy = bx[1], w = bx[2], h = bx[3];
        x1 = cx - w * 0.5f; y1 = cy - h * 0.5f;
        x2 = cx + w * 0.5f; y2 = cy + h * 0.5f;
        ar = w * h;
        f = g_flags[(long)b * Q_ + t];
        if (f & 0xCu) {
            int p = atomicAdd(&cnt, 1);
            tx1[p] = x1; ty1[p] = y1; tx2[p] = x2; ty2[p] = y2; tar[p] = ar;
            tfl[p] = (unsigned char)((f >> 2) & 3u);
        }
    }
    __syncthreads();
    if (t < Q_) {
        int n = cnt;
        unsigned has = 0;
        for (int j = 0; j < n; j++) {
            float xl = fmaxf(x1, tx1[j]), yt = fmaxf(y1, ty1[j]);
            float xr = fminf(x2, tx2[j]), yb = fminf(y2, ty2[j]);
            float inter = fmaxf(xr - xl, 0.f) * fmaxf(yb - yt, 0.f);
            float uni = ar + tar[j] - inter;
            if (inter / uni > 0.5f) {
                has |= (unsigned)tfl[j];
                if (has == 3u) break;
            }
        }
        unsigned cm = 0;
        if ((f & 1u) && !(has & 1u)) cm |= 1u;
        if ((f & 2u) && !(has & 2u)) cm |= 2u;
        g_cand[(long)b * Q_ + t] = (unsigned char)cm;
    }
}

__global__ void k_convert_feat(const float* __restrict__ src)
{
    int i = blockIdx.x * blockDim.x + threadIdx.x;   // float4 index
    if (i >= BQ * (D_ / 4)) return;
    float4 f = ((const float4*)src)[i];
    __nv_bfloat16 h0 = __float2bfloat16(f.x), h1 = __float2bfloat16(f.y);
    __nv_bfloat16 h2 = __float2bfloat16(f.z), h3 = __float2bfloat16(f.w);
    uint2 hp, lp;
    hp.x = (uint32_t)__bfloat16_as_ushort(h0) | ((uint32_t)__bfloat16_as_ushort(h1) << 16);
    hp.y = (uint32_t)__bfloat16_as_ushort(h2) | ((uint32_t)__bfloat16_as_ushort(h3) << 16);
    lp.x = pack2(f.x - __bfloat162float(h0), f.y - __bfloat162float(h1));
    lp.y = pack2(f.z - __bfloat162float(h2), f.w - __bfloat162float(h3));
    ((uint2*)g_xH[0])[i] = hp;
    ((uint2*)g_xL[0])[i] = lp;
}

__global__ void k_convert_w(const float* __restrict__ W, int wSel)
{
    int idx = blockIdx.x * blockDim.x + threadIdx.x;  // 65536
    if (idx >= D_ * D_) return;
    int k = idx >> 8, n = idx & 255;               // W[k][n] row-major
    float x = W[idx];
    __nv_bfloat16 h = __float2bfloat16(x);
    g_wHp[wSel][n * D_ + k] = h;
    g_wLp[wSel][n * D_ + k] = __float2bfloat16(x - __bfloat162float(h));
}

// ---------------------------------------------------------------------------
// Split-bf16 GEMM on mma.sync: C[64000,256] = EPI(A @ W + bias)
//   CTA tile 128M x 256N, K in 4 chunks of 64, 8 warps of 64x64, 256 threads.
//   smem per stage: AH 16K | AL 16K | BH 32K | BL 32K = 96 KB, double buffered.
// EPI: 0 LN+ReLU->planes | 1 raw->planes + score | 2 ReLU->planes | 3 ReLU+delta
// ---------------------------------------------------------------------------
#define STAGE   98304
#define OFF_AL  16384
#define OFF_BH  32768
#define OFF_BL  65536
#define AUXO    196608
#define SMEM_REQ (AUXO + 8192)      // 204800 <= 227 KB

__device__ __forceinline__ void issue_chunk(
    const __nv_bfloat16* aH, const __nv_bfloat16* aL,
    const __nv_bfloat16* wH, const __nv_bfloat16* wL,
    int blockRow, int c, uint32_t bb, int tid)
{
#pragma unroll 1
    for (int s = tid; s < 6144; s += 256) {
        if (s < 2048) {                                   // A: 2 planes x 128 rows x 8 segs
            int plane = s >> 10;
            int r = (s >> 3) & 127;
            int seg = s & 7;
            uint32_t dst = bb + plane * OFF_AL + r * 128 + ((seg * 16) ^ ((r & 7) << 4));
            const __nv_bfloat16* src = (plane ? aL : aH) + (size_t)(blockRow + r) * D_ + c * 64 + seg * 8;
            cp16(dst, src);
        } else {                                          // B: 2 planes x 256 rows x 8 segs
            int s2 = s - 2048;
            int plane = s2 >> 11;
            int n = (s2 >> 3) & 255;
            int seg = s2 & 7;
            uint32_t dst = bb + OFF_BH + plane * 32768 + n * 128 + ((seg * 16) ^ ((n & 7) << 4));
            const __nv_bfloat16* src = (plane ? wL : wH) + (size_t)n * D_ + c * 64 + seg * 8;
            cp16(dst, src);
        }
    }
    CP_COMMIT();
}

template<int EPI>
__global__ void __launch_bounds__(256, 1) k_mmagemm(
    int inSel, int outSel, int wSel,
    const float* __restrict__ bias,
    const float* __restrict__ aux1,   // ln_g | W_s | unused | W_b3
    const float* __restrict__ aux2)   // ln_b | b_s | unused | b_b3
{
    extern __shared__ __align__(1024) char smraw[];
    uint32_t base = smem_u32(smraw);
    int tid = threadIdx.x, wid = tid >> 5, lane = tid & 31;
    int wm = wid & 1, wn = wid >> 1;        // warp tile: 64M x 64N
    int blockRow = blockIdx.x * 128;

    const __nv_bfloat16* aH = g_xH[inSel];
    const __nv_bfloat16* aL = g_xL[inSel];
    const __nv_bfloat16* wH = g_wHp[wSel];
    const __nv_bfloat16* wL = g_wLp[wSel];

    // aux preload
    float* s_bias = (float*)(smraw + AUXO);
    float* s_v1   = (float*)(smraw + AUXO + 1024);
    float* s_v2   = (float*)(smraw + AUXO + 2048);
    float* s_wb3  = (float*)(smraw + AUXO + 3072);     // 4 KB
    s_bias[tid] = bias[tid];
    if (EPI == 0) { s_v1[tid] = aux1[tid]; s_v2[tid] = aux2[tid]; }
    if (EPI == 1) { s_v1[tid] = aux1[tid]; }
    if (EPI == 3) { ((float4*)s_wb3)[tid] = ((const float4*)aux1)[tid]; }

    float acc[4][8][4];
#pragma unroll
    for (int i = 0; i < 4; i++)
#pragma unroll
        for (int j = 0; j < 8; j++)
#pragma unroll
            for (int r = 0; r < 4; r++) acc[i][j][r] = 0.f;

    issue_chunk(aH, aL, wH, wL, blockRow, 0, base, tid);
    issue_chunk(aH, aL, wH, wL, blockRow, 1, base + STAGE, tid);

#pragma unroll 1
    for (int c = 0; c < 4; c++) {
        if (c < 3) CP_WAIT1(); else CP_WAIT0();
        __syncthreads();
        uint32_t bb = base + (c & 1) * STAGE;

#pragma unroll
        for (int ks = 0; ks < 4; ks++) {
            uint32_t Af[4][4], Bh[4][4], Bl[4][4];
            int colb = ((lane >> 4) << 4) | (ks << 5);
            int rl = lane & 15;
#pragma unroll
            for (int i = 0; i < 4; i++) {                  // A-hi frags
                int row = wm * 64 + i * 16 + rl;
                LDSM4(Af[i], bb + row * 128 + (colb ^ ((row & 7) << 4)));
            }
#pragma unroll
            for (int j4 = 0; j4 < 4; j4++) {               // B-hi / B-lo frags
                int n = wn * 64 + j4 * 16 + rl;
                uint32_t off = n * 128 + (colb ^ ((n & 7) << 4));
                LDSM4(Bh[j4], bb + OFF_BH + off);
                LDSM4(Bl[j4], bb + OFF_BL + off);
            }
#pragma unroll
            for (int i = 0; i < 4; i++)
#pragma unroll
                for (int j = 0; j < 8; j++) {
                    int j4 = j >> 1, sel = j & 1;
                    MMA(acc[i][j], Af[i], Bh[j4][sel], Bh[j4][sel + 2]);  // hi*hi
                    MMA(acc[i][j], Af[i], Bl[j4][sel], Bl[j4][sel + 2]);  // hi*lo
                }
#pragma unroll
            for (int i = 0; i < 4; i++) {                  // A-lo frags (reuse regs)
                int row = wm * 64 + i * 16 + rl;
                LDSM4(Af[i], bb + OFF_AL + row * 128 + (colb ^ ((row & 7) << 4)));
            }
#pragma unroll
            for (int i = 0; i < 4; i++)
#pragma unroll
                for (int j = 0; j < 8; j++) {
                    int j4 = j >> 1, sel = j & 1;
                    MMA(acc[i][j], Af[i], Bh[j4][sel], Bh[j4][sel + 2]);  // lo*hi
                }
        }
        __syncthreads();
        if (c + 2 < 4) issue_chunk(aH, aL, wH, wL, blockRow, c + 2, bb, tid);
    }
    __syncthreads();

    // ---------------- epilogue: acc -> smem [128][257] f32 ----------------
    float* epi = (float*)smraw;
    {
        int g = lane >> 2, t = lane & 3;
#pragma unroll
        for (int i = 0; i < 4; i++)
#pragma unroll
            for (int j = 0; j < 8; j++) {
                int row = wm * 64 + i * 16 + g;
                int col = wn * 64 + j * 8 + 2 * t;
                float* p = epi + row * 257 + col;
                p[0] = acc[i][j][0]; p[1] = acc[i][j][1];
                p += 8 * 257;
                p[0] = acc[i][j][2]; p[1] = acc[i][j][3];
            }
    }
    __syncthreads();

    // per-row epilogue: 2 threads per row, 128 cols each
    {
        int r = tid >> 1, half = tid & 1, cb = half * 128;
        int grow = blockRow + r;
        __nv_bfloat16* oH = g_xH[outSel] + (size_t)grow * D_ + cb;
        __nv_bfloat16* oL = g_xL[outSel] + (size_t)grow * D_ + cb;
        const float* row = epi + r * 257;

        if (EPI == 0) {
            float s = 0.f, s2 = 0.f;
#pragma unroll 4
            for (int k = 0; k < 128; k++) {
                float v = row[cb + k] + s_bias[cb + k];
                s += v; s2 += v * v;
            }
            s  += __shfl_xor_sync(0xffffffffu, s, 1);
            s2 += __shfl_xor_sync(0xffffffffu, s2, 1);
            float mu = s * (1.f / 256.f);
            float var = s2 * (1.f / 256.f) - mu * mu;
            float rs = rsqrtf(var + 1e-5f);
#pragma unroll 1
            for (int k0 = 0; k0 < 128; k0 += 8) {
                uint32_t hp[4], lp[4];
#pragma unroll
                for (int p = 0; p < 4; p++) {
                    int c0 = cb + k0 + 2 * p;
                    float v0 = fmaxf(((row[c0]     + s_bias[c0])     - mu) * rs * s_v1[c0]     + s_v2[c0],     0.f);
                    float v1 = fmaxf(((row[c0 + 1] + s_bias[c0 + 1]) - mu) * rs * s_v1[c0 + 1] + s_v2[c0 + 1], 0.f);
                    __nv_bfloat16 h0 = __float2bfloat16(v0), h1 = __float2bfloat16(v1);
                    hp[p] = (uint32_t)__bfloat16_as_ushort(h0) | ((uint32_t)__bfloat16_as_ushort(h1) << 16);
                    lp[p] = pack2(v0 - __bfloat162float(h0), v1 - __bfloat162float(h1));
                }
                *(uint4*)(oH + k0) = make_uint4(hp[0], hp[1], hp[2], hp[3]);
                *(uint4*)(oL + k0) = make_uint4(lp[0], lp[1], lp[2], lp[3]);
            }
        } else if (EPI == 1) {
            float score = 0.f;
#pragma unroll 1
            for (int k0 = 0; k0 < 128; k0 += 8) {
                uint32_t hp[4], lp[4];
#pragma unroll
                for (int p = 0; p < 4; p++) {
                    int c0 = cb + k0 + 2 * p;
                    float v0 = row[c0]     + s_bias[c0];
                    float v1 = row[c0 + 1] + s_bias[c0 + 1];
                    score += v0 * s_v1[c0] + v1 * s_v1[c0 + 1];
                    __nv_bfloat16 h0 = __float2bfloat16(v0), h1 = __float2bfloat16(v1);
                    hp[p] = (uint32_t)__bfloat16_as_ushort(h0) | ((uint32_t)__bfloat16_as_ushort(h1) << 16);
                    lp[p] = pack2(v0 - __bfloat162float(h0), v1 - __bfloat162float(h1));
                }
                *(uint4*)(oH + k0) = make_uint4(hp[0], hp[1], hp[2], hp[3]);
                *(uint4*)(oL + k0) = make_uint4(lp[0], lp[1], lp[2], lp[3]);
            }
            score += __shfl_xor_sync(0xffffffffu, score, 1);
            if (half == 0) g_score[grow] = score + aux2[0];
        } else if (EPI == 2) {
#pragma unroll 1
            for (int k0 = 0; k0 < 128; k0 += 8) {
                uint32_t hp[4], lp[4];
#pragma unroll
                for (int p = 0; p < 4; p++) {
                    int c0 = cb + k0 + 2 * p;
                    float v0 = fmaxf(row[c0]     + s_bias[c0],     0.f);
                    float v1 = fmaxf(row[c0 + 1] + s_bias[c0 + 1], 0.f);
                    __nv_bfloat16 h0 = __float2bfloat16(v0), h1 = __float2bfloat16(v1);
                    hp[p] = (uint32_t)__bfloat16_as_ushort(h0) | ((uint32_t)__bfloat16_as_ushort(h1) << 16);
                    lp[p] = pack2(v0 - __bfloat162float(h0), v1 - __bfloat162float(h1));
                }
                *(uint4*)(oH + k0) = make_uint4(hp[0], hp[1], hp[2], hp[3]);
                *(uint4*)(oL + k0) = make_uint4(lp[0], lp[1], lp[2], lp[3]);
            }
        } else {   // EPI 3: relu + delta, no store
            float p0 = 0.f, p1 = 0.f, p2 = 0.f, p3 = 0.f;
#pragma unroll 4
            for (int k = 0; k < 128; k++) {
                int c0 = cb + k;
                float v = fmaxf(row[c0] + s_bias[c0], 0.f);
                const float* w3 = &s_wb3[c0 * 4];
                p0 += v * w3[0]; p1 += v * w3[1];
                p2 += v * w3[2]; p3 += v * w3[3];
            }
            p0 += __shfl_xor_sync(0xffffffffu, p0, 1);
            p1 += __shfl_xor_sync(0xffffffffu, p1, 1);
            p2 += __shfl_xor_sync(0xffffffffu, p2, 1);
            p3 += __shfl_xor_sync(0xffffffffu, p3, 1);
            if (half == 0) {
                g_delta[(long)grow * 4 + 0] = p0 + aux2[0];
                g_delta[(long)grow * 4 + 1] = p1 + aux2[1];
                g_delta[(long)grow * 4 + 2] = p2 + aux2[2];
                g_delta[(long)grow * 4 + 3] = p3 + aux2[3];
            }
        }
    }
}

// ---------------------------------------------------------------------------
// Finalize: candidate boxes, inverse sigmoid, refine, mask, pack
// ---------------------------------------------------------------------------
__global__ void k_finalize(const float* __restrict__ boxes,
                           float* __restrict__ out, int out_size)
{
    int q = blockIdx.x * blockDim.x + threadIdx.x;
    if (q >= BQ) return;
    float4 bx = *(const float4*)(boxes + (long)q * 4);
    float cx = bx.x, cy = bx.y, w = bx.z, h = bx.w;
    float ny = cy + 0.5f * h, nw = w * 0.8f, nh = h * 0.8f;
    float dd[4];
    dd[0] = g_delta[(long)q * 4 + 0]; dd[1] = g_delta[(long)q * 4 + 1];
    dd[2] = g_delta[(long)q * 4 + 2]; dd[3] = g_delta[(long)q * 4 + 3];
    float sc = g_score[q];
    unsigned cm = g_cand[q];
    float lb[4]  = {cx,            ny, nw, nh};
    float rbx[4] = {cx + 0.1f * w, ny, nw, nh};
#pragma unroll
    for (int s = 0; s < 2; s++) {
        float m = ((cm >> s) & 1u) ? 1.f : 0.f;
        const float* cb = s ? rbx : lb;
        long basei = ((long)q * 2 + s) * 5;
#pragma unroll
        for (int c = 0; c < 4; c++) {
            float x = fminf(fmaxf(cb[c], 0.f), 1.f);
            float inv = logf(fmaxf(x, 1e-5f) / fmaxf(1.f - x, 1e-5f));
            float t = dd[c] + inv;
            out[basei + c] = (1.f / (1.f + expf(-t))) * m;
        }
        out[basei + 4] = sc * m;
        if (out_size >= BQ * 10 + BQ * 2)
            out[BQ * 10 + (long)q * 2 + s] = m;
    }
}

// ---------------------------------------------------------------------------
// Launch
// ---------------------------------------------------------------------------
extern "C" void kernel_launch(void* const* d_in, const int* in_sizes, int n_in,
                              void* d_out, int out_size)
{
    const float* logits   = (const float*)d_in[0];
    const float* boxes    = (const float*)d_in[1];
    const float* features = (const float*)d_in[2];
    const float* W_p1 = (const float*)d_in[4];
    const float* b_p1 = (const float*)d_in[5];
    const float* ln_g = (const float*)d_in[6];
    const float* ln_b = (const float*)d_in[7];
    const float* W_p2 = (const float*)d_in[8];
    const float* b_p2 = (const float*)d_in[9];
    const float* W_b1 = (const float*)d_in[10];
    const float* b_b1 = (const float*)d_in[11];
    const float* W_b2 = (const float*)d_in[12];
    const float* b_b2 = (const float*)d_in[13];
    const float* W_b3 = (const float*)d_in[14];
    const float* b_b3 = (const float*)d_in[15];
    const float* W_s  = (const float*)d_in[16];
    const float* b_s  = (const float*)d_in[17];
    float* out = (float*)d_out;
    (void)in_sizes; (void)n_in;

    cudaFuncSetAttribute(k_mmagemm<0>, cudaFuncAttributeMaxDynamicSharedMemorySize, SMEM_REQ);
    cudaFuncSetAttribute(k_mmagemm<1>, cudaFuncAttributeMaxDynamicSharedMemorySize, SMEM_REQ);
    cudaFuncSetAttribute(k_mmagemm<2>, cudaFuncAttributeMaxDynamicSharedMemorySize, SMEM_REQ);
    cudaFuncSetAttribute(k_mmagemm<3>, cudaFuncAttributeMaxDynamicSharedMemorySize, SMEM_REQ);

    k_flags<<<(BQ + 255) / 256, 256>>>(logits);
    k_mask<<<B_, 1024>>>(boxes);
    k_convert_feat<<<(BQ * (D_ / 4) + 255) / 256, 256>>>(features);
    k_convert_w<<<256, 256>>>(W_p1, 0);
    k_convert_w<<<256, 256>>>(W_p2, 1);
    k_convert_w<<<256, 256>>>(W_b1, 2);
    k_convert_w<<<256, 256>>>(W_b2, 3);

    // G1: hdd = relu(LN(feat@W_p1+b)) : planes0 -> planes1
    k_mmagemm<0><<<500, 256, SMEM_REQ>>>(0, 1, 0, b_p1, ln_g, ln_b);
    // G2: ary = planes1@W_p2+b (raw) + score : planes1 -> planes0
    k_mmagemm<1><<<500, 256, SMEM_REQ>>>(1, 0, 1, b_p2, W_s, b_s);
    // G3: m1 = relu(planes0@W_b1+b) : planes0 -> planes1
    k_mmagemm<2><<<500, 256, SMEM_REQ>>>(0, 1, 2, b_b1, b_b1, b_b1);
    // G4: delta = relu(planes1@W_b2+b)@W_b3 + b_b3 (no store)
    k_mmagemm<3><<<500, 256, SMEM_REQ>>>(1, 0, 3, b_b2, W_b3, b_b3);

    k_finalize<<<(BQ + 255) / 256, 256>>>(boxes, out, out_size);
}

// round 10
// speedup vs baseline: 3.5352x; 2.8493x over previous
#include <cuda_runtime.h>
#include <cuda_bf16.h>
#include <math.h>
#include <stdint.h>

#define B_  64
#define Q_  1000
#define BQ  64000
#define D_  256
#define LOGIT_THR 0.8472978603872034f   // sigmoid(x)>0.7  <=>  x>ln(7/3)

// ---------------------------------------------------------------------------
// Device-global scratch. Compacted activations as separate hi/lo bf16 planes.
// ---------------------------------------------------------------------------
__device__ __nv_bfloat16 g_xH[2][BQ * D_];
__device__ __nv_bfloat16 g_xL[2][BQ * D_];
__device__ __nv_bfloat16 g_wHp[4][D_ * D_];   // transposed weights [n][k]
__device__ __nv_bfloat16 g_wLp[4][D_ * D_];
__device__ float         g_delta[BQ * 4];     // indexed by compacted row
__device__ float         g_score[BQ];         // indexed by compacted row
__device__ unsigned char g_flags[BQ];
__device__ int           g_idx[BQ];           // q | (cand_bits<<16)
__device__ int           g_cnt;

// ---------------------------------------------------------------------------
// PTX helpers (plain-sm_100 legal)
// ---------------------------------------------------------------------------
__device__ __forceinline__ uint32_t smem_u32(const void* p) {
    uint32_t r;
    asm("{ .reg .u64 t; cvta.to.shared.u64 t, %1; cvt.u32.u64 %0, t; }" : "=r"(r) : "l"(p));
    return r;
}
__device__ __forceinline__ void cp16(uint32_t dst, const void* src) {
    asm volatile("cp.async.cg.shared.global [%0], [%1], 16;" :: "r"(dst), "l"(src));
}
#define CP_COMMIT()  asm volatile("cp.async.commit_group;")
#define CP_WAIT0()   asm volatile("cp.async.wait_group 0;")

#define LDSM4(r, addr) \
    asm volatile("ldmatrix.sync.aligned.m8n8.x4.shared.b16 {%0,%1,%2,%3}, [%4];" \
        : "=r"((r)[0]), "=r"((r)[1]), "=r"((r)[2]), "=r"((r)[3]) : "r"(addr))

#define MMA(d, a, b0, b1) \
    asm volatile("mma.sync.aligned.m16n8k16.row.col.f32.bf16.bf16.f32 " \
        "{%0,%1,%2,%3},{%4,%5,%6,%7},{%8,%9},{%0,%1,%2,%3};" \
        : "+f"((d)[0]), "+f"((d)[1]), "+f"((d)[2]), "+f"((d)[3]) \
        : "r"((a)[0]), "r"((a)[1]), "r"((a)[2]), "r"((a)[3]), "r"(b0), "r"(b1))

__device__ __forceinline__ uint32_t pack2(float a, float b) {
    return (uint32_t)__bfloat16_as_ushort(__float2bfloat16(a))
         | ((uint32_t)__bfloat16_as_ushort(__float2bfloat16(b)) << 16);
}

// ---------------------------------------------------------------------------
// k_zero: reset counter + zero output
// ---------------------------------------------------------------------------
__global__ void k_zero(float* __restrict__ out, int out_size)
{
    int i = blockIdx.x * blockDim.x + threadIdx.x;
    if (i == 0) g_cnt = 0;
    int zn4 = ((out_size >= BQ * 10 + BQ * 2) ? (BQ * 10 + BQ * 2) : (BQ * 10)) / 4;
    float4 z = make_float4(0.f, 0.f, 0.f, 0.f);
    float4* o4 = (float4*)out;
    for (int j = i; j < zn4; j += gridDim.x * blockDim.x) o4[j] = z;
}

// ---------------------------------------------------------------------------
// k_convw: split all 4 weights (transposed to [n][k]) in one launch
// ---------------------------------------------------------------------------
__global__ void k_convw(const float* __restrict__ W0, const float* __restrict__ W1,
                        const float* __restrict__ W2, const float* __restrict__ W3)
{
    int wSel = blockIdx.x >> 8;
    int idx = (blockIdx.x & 255) * 256 + threadIdx.x;   // [0, 65536)
    const float* W = (wSel == 0) ? W0 : (wSel == 1) ? W1 : (wSel == 2) ? W2 : W3;
    int k = idx >> 8, n = idx & 255;                    // W[k][n] row-major
    float x = W[idx];
    __nv_bfloat16 h = __float2bfloat16(x);
    g_wHp[wSel][n * D_ + k] = h;
    g_wLp[wSel][n * D_ + k] = __float2bfloat16(x - __bfloat162float(h));
}

// ---------------------------------------------------------------------------
// k_flags
// ---------------------------------------------------------------------------
__global__ void k_flags(const float* __restrict__ logits)
{
    int q = blockIdx.x * blockDim.x + threadIdx.x;
    if (q >= BQ) return;
    const float* l = logits + (long)q * 6;
    unsigned f = 0;
    if (l[0] > LOGIT_THR) f |= 1u;
    if (l[4] > LOGIT_THR) f |= 2u;
    if (l[1] > LOGIT_THR) f |= 4u;
    if (l[5] > LOGIT_THR) f |= 8u;
    g_flags[q] = (unsigned char)f;
}

// ---------------------------------------------------------------------------
// k_mask: IoU candidate mask + fused compaction append
// ---------------------------------------------------------------------------
__global__ void __launch_bounds__(1024) k_mask(const float* __restrict__ boxes)
{
    __shared__ float tx1[Q_], ty1[Q_], tx2[Q_], ty2[Q_], tar[Q_];
    __shared__ unsigned char tfl[Q_];
    __shared__ int cnt;
    int b = blockIdx.x, t = threadIdx.x;
    if (t == 0) cnt = 0;
    __syncthreads();
    float x1 = 0.f, y1 = 0.f, x2 = 0.f, y2 = 0.f, ar = 0.f;
    unsigned f = 0;
    if (t < Q_) {
        const float* bx = boxes + ((long)b * Q_ + t) * 4;
        float cx = bx[0], cy = bx[1], w = bx[2], h = bx[3];
        x1 = cx - w * 0.5f; y1 = cy - h * 0.5f;
        x2 = cx + w * 0.5f; y2 = cy + h * 0.5f;
        ar = w * h;
        f = g_flags[(long)b * Q_ + t];
        if (f & 0xCu) {
            int p = atomicAdd(&cnt, 1);
            tx1[p] = x1; ty1[p] = y1; tx2[p] = x2; ty2[p] = y2; tar[p] = ar;
            tfl[p] = (unsigned char)((f >> 2) & 3u);
        }
    }
    __syncthreads();
    if (t < Q_) {
        int n = cnt;
        unsigned has = 0;
        for (int j = 0; j < n; j++) {
            float xl = fmaxf(x1, tx1[j]), yt = fmaxf(y1, ty1[j]);
            float xr = fminf(x2, tx2[j]), yb = fminf(y2, ty2[j]);
            float inter = fmaxf(xr - xl, 0.f) * fmaxf(yb - yt, 0.f);
            float uni = ar + tar[j] - inter;
            if (inter / uni > 0.5f) {
                has |= (unsigned)tfl[j];
                if (has == 3u) break;
            }
        }
        unsigned cm = 0;
        if ((f & 1u) && !(has & 1u)) cm |= 1u;
        if ((f & 2u) && !(has & 2u)) cm |= 2u;
        if (cm) {
            int pos = atomicAdd(&g_cnt, 1);
            g_idx[pos] = (b * Q_ + t) | ((int)cm << 16);
        }
    }
}

// ---------------------------------------------------------------------------
// k_featgather: gather candidate rows into compacted split planes0
// ---------------------------------------------------------------------------
__global__ void k_featgather(const float* __restrict__ src)
{
    int cnt = g_cnt;
    int total = cnt * 64;           // float4 granules
    int stride = gridDim.x * blockDim.x;
    const float4* s4 = (const float4*)src;
    for (int g = blockIdx.x * blockDim.x + threadIdx.x; g < total; g += stride) {
        int row = g >> 6, col = g & 63;
        int q = g_idx[row] & 0xFFFF;
        float4 f = s4[(size_t)q * 64 + col];
        __nv_bfloat16 h0 = __float2bfloat16(f.x), h1 = __float2bfloat16(f.y);
        __nv_bfloat16 h2 = __float2bfloat16(f.z), h3 = __float2bfloat16(f.w);
        uint2 hp, lp;
        hp.x = (uint32_t)__bfloat16_as_ushort(h0) | ((uint32_t)__bfloat16_as_ushort(h1) << 16);
        hp.y = (uint32_t)__bfloat16_as_ushort(h2) | ((uint32_t)__bfloat16_as_ushort(h3) << 16);
        lp.x = pack2(f.x - __bfloat162float(h0), f.y - __bfloat162float(h1));
        lp.y = pack2(f.z - __bfloat162float(h2), f.w - __bfloat162float(h3));
        ((uint2*)g_xH[0])[(size_t)row * 64 + col] = hp;
        ((uint2*)g_xL[0])[(size_t)row * 64 + col] = lp;
    }
}

// ---------------------------------------------------------------------------
// Split-bf16 GEMM on mma.sync over compacted rows.
//   CTA tile 64M x 256N, K 4x64 chunks, single-stage smem (occ 2).
//   8 warps = 2(wm) x 4(wn), warp tile 32M x 64N, acc[2][8][4] = 64 regs.
// smem stage: AH 8K | AL 8K | BH 32K | BL 32K = 80 KB; aux 8 KB.
// EPI: 0 LN+ReLU->planes | 1 raw->planes+score | 2 ReLU->planes | 3 ReLU+delta
// ---------------------------------------------------------------------------
#define OFF_AL  8192
#define OFF_BH  16384
#define OFF_BL  49152
#define AUXO    81920
#define SMEM_REQ (AUXO + 8192)      // 90112 -> 2 CTAs/SM

__device__ __forceinline__ void load_chunk64(
    const __nv_bfloat16* aH, const __nv_bfloat16* aL,
    const __nv_bfloat16* wH, const __nv_bfloat16* wL,
    int blockRow, int c, uint32_t bb, int tid)
{
#pragma unroll 1
    for (int s = tid; s < 5120; s += 256) {
        if (s < 1024) {                                   // A: 2 planes x 64 rows x 8 segs
            int plane = s >> 9, r = (s >> 3) & 63, seg = s & 7;
            uint32_t dst = bb + plane * OFF_AL + r * 128 + ((seg * 16) ^ ((r & 7) << 4));
            const __nv_bfloat16* src = (plane ? aL : aH) + (size_t)(blockRow + r) * D_ + c * 64 + seg * 8;
            cp16(dst, src);
        } else {                                          // B: 2 planes x 256 n x 8 segs
            int s2 = s - 1024;
            int plane = s2 >> 11, n = (s2 >> 3) & 255, seg = s2 & 7;
            uint32_t dst = bb + OFF_BH + plane * 32768 + n * 128 + ((seg * 16) ^ ((n & 7) << 4));
            const __nv_bfloat16* src = (plane ? wL : wH) + (size_t)n * D_ + c * 64 + seg * 8;
            cp16(dst, src);
        }
    }
    CP_COMMIT();
}

template<int EPI>
__global__ void __launch_bounds__(256, 2) k_mmagemm(
    int inSel, int outSel, int wSel,
    const float* __restrict__ bias,
    const float* __restrict__ aux1,   // ln_g | W_s | unused | W_b3
    const float* __restrict__ aux2)   // ln_b | b_s | unused | b_b3
{
    int cnt = g_cnt;
    int blockRow = blockIdx.x * 64;
    if (blockRow >= cnt) return;

    extern __shared__ __align__(1024) char smraw[];
    uint32_t base = smem_u32(smraw);
    int tid = threadIdx.x, wid = tid >> 5, lane = tid & 31;
    int wm = wid & 1, wn = wid >> 1;        // warp tile 32M x 64N

    const __nv_bfloat16* aH = g_xH[inSel];
    const __nv_bfloat16* aL = g_xL[inSel];
    const __nv_bfloat16* wH = g_wHp[wSel];
    const __nv_bfloat16* wL = g_wLp[wSel];

    float* s_bias = (float*)(smraw + AUXO);
    float* s_v1   = (float*)(smraw + AUXO + 1024);
    float* s_v2   = (float*)(smraw + AUXO + 2048);
    float* s_wb3  = (float*)(smraw + AUXO + 3072);
    s_bias[tid] = bias[tid];
    if (EPI == 0) { s_v1[tid] = aux1[tid]; s_v2[tid] = aux2[tid]; }
    if (EPI == 1) { s_v1[tid] = aux1[tid]; }
    if (EPI == 3) { ((float4*)s_wb3)[tid] = ((const float4*)aux1)[tid]; }

    float acc[2][8][4];
#pragma unroll
    for (int i = 0; i < 2; i++)
#pragma unroll
        for (int j = 0; j < 8; j++)
#pragma unroll
            for (int r = 0; r < 4; r++) acc[i][j][r] = 0.f;

#pragma unroll 1
    for (int c = 0; c < 4; c++) {
        load_chunk64(aH, aL, wH, wL, blockRow, c, base, tid);
        CP_WAIT0();
        __syncthreads();

#pragma unroll
        for (int ks = 0; ks < 4; ks++) {
            uint32_t Af[2][4], Bh[4][4], Bl[4][4];
            int colb = ((lane >> 4) << 4) | (ks << 5);
            int rl = lane & 15;
#pragma unroll
            for (int i = 0; i < 2; i++) {                  // A-hi
                int row = wm * 32 + i * 16 + rl;
                LDSM4(Af[i], base + row * 128 + (colb ^ ((row & 7) << 4)));
            }
#pragma unroll
            for (int j4 = 0; j4 < 4; j4++) {               // B-hi / B-lo
                int n = wn * 64 + j4 * 16 + rl;
                uint32_t off = n * 128 + (colb ^ ((n & 7) << 4));
                LDSM4(Bh[j4], base + OFF_BH + off);
                LDSM4(Bl[j4], base + OFF_BL + off);
            }
#pragma unroll
            for (int i = 0; i < 2; i++)
#pragma unroll
                for (int j = 0; j < 8; j++) {
                    int j4 = j >> 1, sel = j & 1;
                    MMA(acc[i][j], Af[i], Bh[j4][sel], Bh[j4][sel + 2]);  // hi*hi
                    MMA(acc[i][j], Af[i], Bl[j4][sel], Bl[j4][sel + 2]);  // hi*lo
                }
#pragma unroll
            for (int i = 0; i < 2; i++) {                  // A-lo
                int row = wm * 32 + i * 16 + rl;
                LDSM4(Af[i], base + OFF_AL + row * 128 + (colb ^ ((row & 7) << 4)));
            }
#pragma unroll
            for (int i = 0; i < 2; i++)
#pragma unroll
                for (int j = 0; j < 8; j++) {
                    int j4 = j >> 1, sel = j & 1;
                    MMA(acc[i][j], Af[i], Bh[j4][sel], Bh[j4][sel + 2]);  // lo*hi
                }
        }
        __syncthreads();
    }

    // ---------------- epilogue: acc -> smem [64][257] f32 ----------------
    float* epi = (float*)smraw;
    {
        int g = lane >> 2, t = lane & 3;
#pragma unroll
        for (int i = 0; i < 2; i++)
#pragma unroll
            for (int j = 0; j < 8; j++) {
                int row = wm * 32 + i * 16 + g;
                int col = wn * 64 + j * 8 + 2 * t;
                float* p = epi + row * 257 + col;
                p[0] = acc[i][j][0]; p[1] = acc[i][j][1];
                p += 8 * 257;
                p[0] = acc[i][j][2]; p[1] = acc[i][j][3];
            }
    }
    __syncthreads();

    // per-row epilogue: 4 threads/row, 64 cols each
    {
        int r = tid >> 2, quarter = tid & 3, cb = quarter * 64;
        int grow = blockRow + r;
        __nv_bfloat16* oH = g_xH[outSel] + (size_t)grow * D_ + cb;
        __nv_bfloat16* oL = g_xL[outSel] + (size_t)grow * D_ + cb;
        const float* row = epi + r * 257;

        if (EPI == 0) {
            float s = 0.f, s2 = 0.f;
#pragma unroll 4
            for (int k = 0; k < 64; k++) {
                float v = row[cb + k] + s_bias[cb + k];
                s += v; s2 += v * v;
            }
            s  += __shfl_xor_sync(0xffffffffu, s, 1);
            s  += __shfl_xor_sync(0xffffffffu, s, 2);
            s2 += __shfl_xor_sync(0xffffffffu, s2, 1);
            s2 += __shfl_xor_sync(0xffffffffu, s2, 2);
            float mu = s * (1.f / 256.f);
            float var = s2 * (1.f / 256.f) - mu * mu;
            float rs = rsqrtf(var + 1e-5f);
#pragma unroll 1
            for (int k0 = 0; k0 < 64; k0 += 8) {
                uint32_t hp[4], lp[4];
#pragma unroll
                for (int p = 0; p < 4; p++) {
                    int c0 = cb + k0 + 2 * p;
                    float v0 = fmaxf(((row[c0]     + s_bias[c0])     - mu) * rs * s_v1[c0]     + s_v2[c0],     0.f);
                    float v1 = fmaxf(((row[c0 + 1] + s_bias[c0 + 1]) - mu) * rs * s_v1[c0 + 1] + s_v2[c0 + 1], 0.f);
                    __nv_bfloat16 h0 = __float2bfloat16(v0), h1 = __float2bfloat16(v1);
                    hp[p] = (uint32_t)__bfloat16_as_ushort(h0) | ((uint32_t)__bfloat16_as_ushort(h1) << 16);
                    lp[p] = pack2(v0 - __bfloat162float(h0), v1 - __bfloat162float(h1));
                }
                *(uint4*)(oH + k0) = make_uint4(hp[0], hp[1], hp[2], hp[3]);
                *(uint4*)(oL + k0) = make_uint4(lp[0], lp[1], lp[2], lp[3]);
            }
        } else if (EPI == 1) {
            float score = 0.f;
#pragma unroll 1
            for (int k0 = 0; k0 < 64; k0 += 8) {
                uint32_t hp[4], lp[4];
#pragma unroll
                for (int p = 0; p < 4; p++) {
                    int c0 = cb + k0 + 2 * p;
                    float v0 = row[c0]     + s_bias[c0];
                    float v1 = row[c0 + 1] + s_bias[c0 + 1];
                    score += v0 * s_v1[c0] + v1 * s_v1[c0 + 1];
                    __nv_bfloat16 h0 = __float2bfloat16(v0), h1 = __float2bfloat16(v1);
                    hp[p] = (uint32_t)__bfloat16_as_ushort(h0) | ((uint32_t)__bfloat16_as_ushort(h1) << 16);
                    lp[p] = pack2(v0 - __bfloat162float(h0), v1 - __bfloat162float(h1));
                }
                *(uint4*)(oH + k0) = make_uint4(hp[0], hp[1], hp[2], hp[3]);
                *(uint4*)(oL + k0) = make_uint4(lp[0], lp[1], lp[2], lp[3]);
            }
            score += __shfl_xor_sync(0xffffffffu, score, 1);
            score += __shfl_xor_sync(0xffffffffu, score, 2);
            if (quarter == 0) g_score[grow] = score + aux2[0];
        } else if (EPI == 2) {
#pragma unroll 1
            for (int k0 = 0; k0 < 64; k0 += 8) {
                uint32_t hp[4], lp[4];
#pragma unroll
                for (int p = 0; p < 4; p++) {
                    int c0 = cb + k0 + 2 * p;
                    float v0 = fmaxf(row[c0]     + s_bias[c0],     0.f);
                    float v1 = fmaxf(row[c0 + 1] + s_bias[c0 + 1], 0.f);
                    __nv_bfloat16 h0 = __float2bfloat16(v0), h1 = __float2bfloat16(v1);
                    hp[p] = (uint32_t)__bfloat16_as_ushort(h0) | ((uint32_t)__bfloat16_as_ushort(h1) << 16);
                    lp[p] = pack2(v0 - __bfloat162float(h0), v1 - __bfloat162float(h1));
                }
                *(uint4*)(oH + k0) = make_uint4(hp[0], hp[1], hp[2], hp[3]);
                *(uint4*)(oL + k0) = make_uint4(lp[0], lp[1], lp[2], lp[3]);
            }
        } else {   // EPI 3: relu + fused delta
            float p0 = 0.f, p1 = 0.f, p2 = 0.f, p3 = 0.f;
#pragma unroll 4
            for (int k = 0; k < 64; k++) {
                int c0 = cb + k;
                float v = fmaxf(row[c0] + s_bias[c0], 0.f);
                const float* w3 = &s_wb3[c0 * 4];
                p0 += v * w3[0]; p1 += v * w3[1];
                p2 += v * w3[2]; p3 += v * w3[3];
            }
            p0 += __shfl_xor_sync(0xffffffffu, p0, 1);
            p0 += __shfl_xor_sync(0xffffffffu, p0, 2);
            p1 += __shfl_xor_sync(0xffffffffu, p1, 1);
            p1 += __shfl_xor_sync(0xffffffffu, p1, 2);
            p2 += __shfl_xor_sync(0xffffffffu, p2, 1);
            p2 += __shfl_xor_sync(0xffffffffu, p2, 2);
            p3 += __shfl_xor_sync(0xffffffffu, p3, 1);
            p3 += __shfl_xor_sync(0xffffffffu, p3, 2);
            if (quarter == 0) {
                g_delta[(long)grow * 4 + 0] = p0 + aux2[0];
                g_delta[(long)grow * 4 + 1] = p1 + aux2[1];
                g_delta[(long)grow * 4 + 2] = p2 + aux2[2];
                g_delta[(long)grow * 4 + 3] = p3 + aux2[3];
            }
        }
    }
}

// ---------------------------------------------------------------------------
// k_finalize: scatter candidate results to output (zeros prefilled)
// ---------------------------------------------------------------------------
__global__ void k_finalize(const float* __restrict__ boxes,
                           float* __restrict__ out, int out_size)
{
    int cnt = g_cnt;
    int stride = gridDim.x * blockDim.x;
    for (int i = blockIdx.x * blockDim.x + threadIdx.x; i < cnt; i += stride) {
        int v = g_idx[i];
        int q = v & 0xFFFF;
        unsigned cm = (unsigned)(v >> 16);
        float4 bx = *(const float4*)(boxes + (long)q * 4);
        float cx = bx.x, cy = bx.y, w = bx.z, h = bx.w;
        float ny = cy + 0.5f * h, nw = w * 0.8f, nh = h * 0.8f;
        float dd[4];
        dd[0] = g_delta[(long)i * 4 + 0]; dd[1] = g_delta[(long)i * 4 + 1];
        dd[2] = g_delta[(long)i * 4 + 2]; dd[3] = g_delta[(long)i * 4 + 3];
        float sc = g_score[i];
        float lb[4]  = {cx,            ny, nw, nh};
        float rbx[4] = {cx + 0.1f * w, ny, nw, nh};
#pragma unroll
        for (int s = 0; s < 2; s++) {
            if (!((cm >> s) & 1u)) continue;
            const float* cb = s ? rbx : lb;
            long basei = ((long)q * 2 + s) * 5;
#pragma unroll
            for (int c = 0; c < 4; c++) {
                float x = fminf(fmaxf(cb[c], 0.f), 1.f);
                float inv = logf(fmaxf(x, 1e-5f) / fmaxf(1.f - x, 1e-5f));
                float t = dd[c] + inv;
                out[basei + c] = 1.f / (1.f + expf(-t));
            }
            out[basei + 4] = sc;
            if (out_size >= BQ * 10 + BQ * 2)
                out[BQ * 10 + (long)q * 2 + s] = 1.f;
        }
    }
}

// ---------------------------------------------------------------------------
// Launch. Order puts GEMM-1 at launch #6 so ncu (-s 5 -c 1) profiles it.
// ---------------------------------------------------------------------------
extern "C" void kernel_launch(void* const* d_in, const int* in_sizes, int n_in,
                              void* d_out, int out_size)
{
    const float* logits   = (const float*)d_in[0];
    const float* boxes    = (const float*)d_in[1];
    const float* features = (const float*)d_in[2];
    const float* W_p1 = (const float*)d_in[4];
    const float* b_p1 = (const float*)d_in[5];
    const float* ln_g = (const float*)d_in[6];
    const float* ln_b = (const float*)d_in[7];
    const float* W_p2 = (const float*)d_in[8];
    const float* b_p2 = (const float*)d_in[9];
    const float* W_b1 = (const float*)d_in[10];
    const float* b_b1 = (const float*)d_in[11];
    const float* W_b2 = (const float*)d_in[12];
    const float* b_b2 = (const float*)d_in[13];
    const float* W_b3 = (const float*)d_in[14];
    const float* b_b3 = (const float*)d_in[15];
    const float* W_s  = (const float*)d_in[16];
    const float* b_s  = (const float*)d_in[17];
    float* out = (float*)d_out;
    (void)in_sizes; (void)n_in;

    cudaFuncSetAttribute(k_mmagemm<0>, cudaFuncAttributeMaxDynamicSharedMemorySize, SMEM_REQ);
    cudaFuncSetAttribute(k_mmagemm<1>, cudaFuncAttributeMaxDynamicSharedMemorySize, SMEM_REQ);
    cudaFuncSetAttribute(k_mmagemm<2>, cudaFuncAttributeMaxDynamicSharedMemorySize, SMEM_REQ);
    cudaFuncSetAttribute(k_mmagemm<3>, cudaFuncAttributeMaxDynamicSharedMemorySize, SMEM_REQ);

    k_zero<<<750, 256>>>(out, out_size);                               // 1
    k_convw<<<1024, 256>>>(W_p1, W_p2, W_b1, W_b2);                    // 2
    k_flags<<<(BQ + 255) / 256, 256>>>(logits);                        // 3
    k_mask<<<B_, 1024>>>(boxes);                                       // 4
    k_featgather<<<1000, 256>>>(features);                             // 5

    // G1: hdd = relu(LN(feat@W_p1+b)) : planes0 -> planes1            // 6 (ncu)
    k_mmagemm<0><<<1000, 256, SMEM_REQ>>>(0, 1, 0, b_p1, ln_g, ln_b);
    // G2: ary = planes1@W_p2+b (raw) + score : planes1 -> planes0
    k_mmagemm<1><<<1000, 256, SMEM_REQ>>>(1, 0, 1, b_p2, W_s, b_s);
    // G3: m1 = relu(planes0@W_b1+b) : planes0 -> planes1
    k_mmagemm<2><<<1000, 256, SMEM_REQ>>>(0, 1, 2, b_b1, b_b1, b_b1);
    // G4: delta = relu(planes1@W_b2+b)@W_b3 + b_b3
    k_mmagemm<3><<<1000, 256, SMEM_REQ>>>(1, 0, 3, b_b2, W_b3, b_b3);

    k_finalize<<<250, 256>>>(boxes, out, out_size);
}

// round 11
// speedup vs baseline: 6.7674x; 1.9143x over previous
#include <cuda_runtime.h>
#include <cuda_bf16.h>
#include <math.h>
#include <stdint.h>

#define B_  64
#define Q_  1000
#define BQ  64000
#define D_  256
#define LOGIT_THR 0.8472978603872034f   // sigmoid(x)>0.7  <=>  x>ln(7/3)

// ---------------------------------------------------------------------------
// Device-global scratch. Compacted activations as separate hi/lo bf16 planes.
// ---------------------------------------------------------------------------
__device__ __nv_bfloat16 g_xH[2][BQ * D_];
__device__ __nv_bfloat16 g_xL[2][BQ * D_];
__device__ __nv_bfloat16 g_wHp[4][D_ * D_];   // transposed weights [n][k]
__device__ __nv_bfloat16 g_wLp[4][D_ * D_];
__device__ float         g_delta[BQ * 4];     // indexed by compacted row
__device__ float         g_score[BQ];         // indexed by compacted row
__device__ int           g_idx[BQ];           // q | (cand_bits<<16)
__device__ int           g_cnt;

// ---------------------------------------------------------------------------
// PTX helpers (plain-sm_100 legal)
// ---------------------------------------------------------------------------
__device__ __forceinline__ uint32_t smem_u32(const void* p) {
    uint32_t r;
    asm("{ .reg .u64 t; cvta.to.shared.u64 t, %1; cvt.u32.u64 %0, t; }" : "=r"(r) : "l"(p));
    return r;
}
__device__ __forceinline__ void cp16(uint32_t dst, const void* src) {
    asm volatile("cp.async.cg.shared.global [%0], [%1], 16;" :: "r"(dst), "l"(src));
}
#define CP_COMMIT()  asm volatile("cp.async.commit_group;")
#define CP_WAIT0()   asm volatile("cp.async.wait_group 0;")

#define LDSM4(r, addr) \
    asm volatile("ldmatrix.sync.aligned.m8n8.x4.shared.b16 {%0,%1,%2,%3}, [%4];" \
        : "=r"((r)[0]), "=r"((r)[1]), "=r"((r)[2]), "=r"((r)[3]) : "r"(addr))

#define MMA(d, a, b0, b1) \
    asm volatile("mma.sync.aligned.m16n8k16.row.col.f32.bf16.bf16.f32 " \
        "{%0,%1,%2,%3},{%4,%5,%6,%7},{%8,%9},{%0,%1,%2,%3};" \
        : "+f"((d)[0]), "+f"((d)[1]), "+f"((d)[2]), "+f"((d)[3]) \
        : "r"((a)[0]), "r"((a)[1]), "r"((a)[2]), "r"((a)[3]), "r"(b0), "r"(b1))

__device__ __forceinline__ uint32_t pack2(float a, float b) {
    return (uint32_t)__bfloat16_as_ushort(__float2bfloat16(a))
         | ((uint32_t)__bfloat16_as_ushort(__float2bfloat16(b)) << 16);
}

// ---------------------------------------------------------------------------
// k_zero: reset counter + zero output
// ---------------------------------------------------------------------------
__global__ void k_zero(float* __restrict__ out, int out_size)
{
    int i = blockIdx.x * blockDim.x + threadIdx.x;
    if (i == 0) g_cnt = 0;
    int zn4 = ((out_size >= BQ * 10 + BQ * 2) ? (BQ * 10 + BQ * 2) : (BQ * 10)) / 4;
    float4 z = make_float4(0.f, 0.f, 0.f, 0.f);
    float4* o4 = (float4*)out;
    for (int j = i; j < zn4; j += gridDim.x * blockDim.x) o4[j] = z;
}

// ---------------------------------------------------------------------------
// k_convw: split all 4 weights (transposed to [n][k]) in one launch
// ---------------------------------------------------------------------------
__global__ void k_convw(const float* __restrict__ W0, const float* __restrict__ W1,
                        const float* __restrict__ W2, const float* __restrict__ W3)
{
    int wSel = blockIdx.x >> 8;
    int idx = (blockIdx.x & 255) * 256 + threadIdx.x;   // [0, 65536)
    const float* W = (wSel == 0) ? W0 : (wSel == 1) ? W1 : (wSel == 2) ? W2 : W3;
    int k = idx >> 8, n = idx & 255;                    // W[k][n] row-major
    float x = W[idx];
    __nv_bfloat16 h = __float2bfloat16(x);
    g_wHp[wSel][n * D_ + k] = h;
    g_wLp[wSel][n * D_ + k] = __float2bfloat16(x - __bfloat162float(h));
}

// ---------------------------------------------------------------------------
// k_mask: fused flags + IoU candidate mask + compaction.
//   grid = B_*2 (2 fold-slices per batch). Each block rebuilds the arytenoid
//   target list for its batch, compacts fold queries of its slice into smem,
//   then 4 threads per fold query stride the targets (divide-free predicate).
// ---------------------------------------------------------------------------
__global__ void __launch_bounds__(1024) k_mask(const float* __restrict__ logits,
                                               const float* __restrict__ boxes)
{
    __shared__ float tx1[Q_], ty1[Q_], tx2[Q_], ty2[Q_], tar[Q_];
    __shared__ unsigned char tfl[Q_];
    __shared__ int s_fq[512];
    __shared__ int tn, fn;

    int b = blockIdx.x >> 1, slice = blockIdx.x & 1;
    int t = threadIdx.x;
    if (t == 0) { tn = 0; fn = 0; }
    __syncthreads();

    if (t < Q_) {
        const float* l = logits + ((long)b * Q_ + t) * 6;
        unsigned f = 0;
        if (l[0] > LOGIT_THR) f |= 1u;   // left_fold  (VF_L=0)
        if (l[4] > LOGIT_THR) f |= 2u;   // right_fold (VF_R=4)
        if (l[1] > LOGIT_THR) f |= 4u;   // left_ary   (ARY_L=1)
        if (l[5] > LOGIT_THR) f |= 8u;   // right_ary  (ARY_R=5)
        if (f) {
            const float* bx = boxes + ((long)b * Q_ + t) * 4;
            float cx = bx[0], cy = bx[1], w = bx[2], h = bx[3];
            if (f & 0xCu) {                               // arytenoid target
                int p = atomicAdd(&tn, 1);
                tx1[p] = cx - 0.5f * w; ty1[p] = cy - 0.5f * h;
                tx2[p] = cx + 0.5f * w; ty2[p] = cy + 0.5f * h;
                tar[p] = w * h;
                tfl[p] = (unsigned char)((f >> 2) & 3u);
            }
            if ((f & 3u) && ((t >> 9) == slice)) {        // fold query in slice
                int p = atomicAdd(&fn, 1);
                s_fq[p] = t | (int)((f & 3u) << 16);
            }
        }
    }
    __syncthreads();

    int nt = tn, nf = fn;
    int sub = t & 3;
    unsigned pm = 0xFu << (t & 28);     // quad lane-mask within warp

    for (int e = t >> 2; e < nf; e += 256) {
        int v = s_fq[e];
        int q = v & 0xFFFF;
        unsigned need = (unsigned)(v >> 16) & 3u;
        const float4 bx = *(const float4*)(boxes + ((long)b * Q_ + q) * 4);
        float x1 = bx.x - 0.5f * bx.z, y1 = bx.y - 0.5f * bx.w;
        float x2 = bx.x + 0.5f * bx.z, y2 = bx.y + 0.5f * bx.w;
        float ar = bx.z * bx.w;
        unsigned has = 0;
        for (int j = sub; j < nt; j += 4) {
            float xl = fmaxf(x1, tx1[j]), yt = fmaxf(y1, ty1[j]);
            float xr = fminf(x2, tx2[j]), yb = fminf(y2, ty2[j]);
            float inter = fmaxf(xr - xl, 0.f) * fmaxf(yb - yt, 0.f);
            float uni = ar + tar[j] - inter;
            if (inter > 0.5f * uni) {                     // == inter/uni > 0.5 (uni>0)
                has |= (unsigned)tfl[j];
                if ((has & need) == need) break;
            }
        }
        has |= __shfl_xor_sync(pm, has, 1);
        has |= __shfl_xor_sync(pm, has, 2);
        if (sub == 0) {
            unsigned cm = need & ~has;
            if (cm) {
                int pos = atomicAdd(&g_cnt, 1);
                g_idx[pos] = (b * Q_ + q) | ((int)cm << 16);
            }
        }
    }
}

// ---------------------------------------------------------------------------
// k_featgather: gather candidate rows into compacted split planes0
// ---------------------------------------------------------------------------
__global__ void k_featgather(const float* __restrict__ src)
{
    int cnt = g_cnt;
    int total = cnt * 64;           // float4 granules
    int stride = gridDim.x * blockDim.x;
    const float4* s4 = (const float4*)src;
    for (int g = blockIdx.x * blockDim.x + threadIdx.x; g < total; g += stride) {
        int row = g >> 6, col = g & 63;
        int q = g_idx[row] & 0xFFFF;
        float4 f = s4[(size_t)q * 64 + col];
        __nv_bfloat16 h0 = __float2bfloat16(f.x), h1 = __float2bfloat16(f.y);
        __nv_bfloat16 h2 = __float2bfloat16(f.z), h3 = __float2bfloat16(f.w);
        uint2 hp, lp;
        hp.x = (uint32_t)__bfloat16_as_ushort(h0) | ((uint32_t)__bfloat16_as_ushort(h1) << 16);
        hp.y = (uint32_t)__bfloat16_as_ushort(h2) | ((uint32_t)__bfloat16_as_ushort(h3) << 16);
        lp.x = pack2(f.x - __bfloat162float(h0), f.y - __bfloat162float(h1));
        lp.y = pack2(f.z - __bfloat162float(h2), f.w - __bfloat162float(h3));
        ((uint2*)g_xH[0])[(size_t)row * 64 + col] = hp;
        ((uint2*)g_xL[0])[(size_t)row * 64 + col] = lp;
    }
}

// ---------------------------------------------------------------------------
// Split-bf16 GEMM on mma.sync over compacted rows (unchanged from R10).
//   CTA tile 64M x 256N, K 4x64 chunks, single-stage smem (occ 2).
// ---------------------------------------------------------------------------
#define OFF_AL  8192
#define OFF_BH  16384
#define OFF_BL  49152
#define AUXO    81920
#define SMEM_REQ (AUXO + 8192)      // 90112 -> 2 CTAs/SM

__device__ __forceinline__ void load_chunk64(
    const __nv_bfloat16* aH, const __nv_bfloat16* aL,
    const __nv_bfloat16* wH, const __nv_bfloat16* wL,
    int blockRow, int c, uint32_t bb, int tid)
{
#pragma unroll 1
    for (int s = tid; s < 5120; s += 256) {
        if (s < 1024) {                                   // A: 2 planes x 64 rows x 8 segs
            int plane = s >> 9, r = (s >> 3) & 63, seg = s & 7;
            uint32_t dst = bb + plane * OFF_AL + r * 128 + ((seg * 16) ^ ((r & 7) << 4));
            const __nv_bfloat16* src = (plane ? aL : aH) + (size_t)(blockRow + r) * D_ + c * 64 + seg * 8;
            cp16(dst, src);
        } else {                                          // B: 2 planes x 256 n x 8 segs
            int s2 = s - 1024;
            int plane = s2 >> 11, n = (s2 >> 3) & 255, seg = s2 & 7;
            uint32_t dst = bb + OFF_BH + plane * 32768 + n * 128 + ((seg * 16) ^ ((n & 7) << 4));
            const __nv_bfloat16* src = (plane ? wL : wH) + (size_t)n * D_ + c * 64 + seg * 8;
            cp16(dst, src);
        }
    }
    CP_COMMIT();
}

template<int EPI>
__global__ void __launch_bounds__(256, 2) k_mmagemm(
    int inSel, int outSel, int wSel,
    const float* __restrict__ bias,
    const float* __restrict__ aux1,   // ln_g | W_s | unused | W_b3
    const float* __restrict__ aux2)   // ln_b | b_s | unused | b_b3
{
    int cnt = g_cnt;
    int blockRow = blockIdx.x * 64;
    if (blockRow >= cnt) return;

    extern __shared__ __align__(1024) char smraw[];
    uint32_t base = smem_u32(smraw);
    int tid = threadIdx.x, wid = tid >> 5, lane = tid & 31;
    int wm = wid & 1, wn = wid >> 1;        // warp tile 32M x 64N

    const __nv_bfloat16* aH = g_xH[inSel];
    const __nv_bfloat16* aL = g_xL[inSel];
    const __nv_bfloat16* wH = g_wHp[wSel];
    const __nv_bfloat16* wL = g_wLp[wSel];

    float* s_bias = (float*)(smraw + AUXO);
    float* s_v1   = (float*)(smraw + AUXO + 1024);
    float* s_v2   = (float*)(smraw + AUXO + 2048);
    float* s_wb3  = (float*)(smraw + AUXO + 3072);
    s_bias[tid] = bias[tid];
    if (EPI == 0) { s_v1[tid] = aux1[tid]; s_v2[tid] = aux2[tid]; }
    if (EPI == 1) { s_v1[tid] = aux1[tid]; }
    if (EPI == 3) { ((float4*)s_wb3)[tid] = ((const float4*)aux1)[tid]; }

    float acc[2][8][4];
#pragma unroll
    for (int i = 0; i < 2; i++)
#pragma unroll
        for (int j = 0; j < 8; j++)
#pragma unroll
            for (int r = 0; r < 4; r++) acc[i][j][r] = 0.f;

#pragma unroll 1
    for (int c = 0; c < 4; c++) {
        load_chunk64(aH, aL, wH, wL, blockRow, c, base, tid);
        CP_WAIT0();
        __syncthreads();

#pragma unroll
        for (int ks = 0; ks < 4; ks++) {
            uint32_t Af[2][4], Bh[4][4], Bl[4][4];
            int colb = ((lane >> 4) << 4) | (ks << 5);
            int rl = lane & 15;
#pragma unroll
            for (int i = 0; i < 2; i++) {                  // A-hi
                int row = wm * 32 + i * 16 + rl;
                LDSM4(Af[i], base + row * 128 + (colb ^ ((row & 7) << 4)));
            }
#pragma unroll
            for (int j4 = 0; j4 < 4; j4++) {               // B-hi / B-lo
                int n = wn * 64 + j4 * 16 + rl;
                uint32_t off = n * 128 + (colb ^ ((n & 7) << 4));
                LDSM4(Bh[j4], base + OFF_BH + off);
                LDSM4(Bl[j4], base + OFF_BL + off);
            }
#pragma unroll
            for (int i = 0; i < 2; i++)
#pragma unroll
                for (int j = 0; j < 8; j++) {
                    int j4 = j >> 1, sel = j & 1;
                    MMA(acc[i][j], Af[i], Bh[j4][sel], Bh[j4][sel + 2]);  // hi*hi
                    MMA(acc[i][j], Af[i], Bl[j4][sel], Bl[j4][sel + 2]);  // hi*lo
                }
#pragma unroll
            for (int i = 0; i < 2; i++) {                  // A-lo
                int row = wm * 32 + i * 16 + rl;
                LDSM4(Af[i], base + OFF_AL + row * 128 + (colb ^ ((row & 7) << 4)));
            }
#pragma unroll
            for (int i = 0; i < 2; i++)
#pragma unroll
                for (int j = 0; j < 8; j++) {
                    int j4 = j >> 1, sel = j & 1;
                    MMA(acc[i][j], Af[i], Bh[j4][sel], Bh[j4][sel + 2]);  // lo*hi
                }
        }
        __syncthreads();
    }

    // ---------------- epilogue: acc -> smem [64][257] f32 ----------------
    float* epi = (float*)smraw;
    {
        int g = lane >> 2, t = lane & 3;
#pragma unroll
        for (int i = 0; i < 2; i++)
#pragma unroll
            for (int j = 0; j < 8; j++) {
                int row = wm * 32 + i * 16 + g;
                int col = wn * 64 + j * 8 + 2 * t;
                float* p = epi + row * 257 + col;
                p[0] = acc[i][j][0]; p[1] = acc[i][j][1];
                p += 8 * 257;
                p[0] = acc[i][j][2]; p[1] = acc[i][j][3];
            }
    }
    __syncthreads();

    // per-row epilogue: 4 threads/row, 64 cols each
    {
        int r = tid >> 2, quarter = tid & 3, cb = quarter * 64;
        int grow = blockRow + r;
        __nv_bfloat16* oH = g_xH[outSel] + (size_t)grow * D_ + cb;
        __nv_bfloat16* oL = g_xL[outSel] + (size_t)grow * D_ + cb;
        const float* row = epi + r * 257;

        if (EPI == 0) {
            float s = 0.f, s2 = 0.f;
#pragma unroll 4
            for (int k = 0; k < 64; k++) {
                float v = row[cb + k] + s_bias[cb + k];
                s += v; s2 += v * v;
            }
            s  += __shfl_xor_sync(0xffffffffu, s, 1);
            s  += __shfl_xor_sync(0xffffffffu, s, 2);
            s2 += __shfl_xor_sync(0xffffffffu, s2, 1);
            s2 += __shfl_xor_sync(0xffffffffu, s2, 2);
            float mu = s * (1.f / 256.f);
            float var = s2 * (1.f / 256.f) - mu * mu;
            float rs = rsqrtf(var + 1e-5f);
#pragma unroll 1
            for (int k0 = 0; k0 < 64; k0 += 8) {
                uint32_t hp[4], lp[4];
#pragma unroll
                for (int p = 0; p < 4; p++) {
                    int c0 = cb + k0 + 2 * p;
                    float v0 = fmaxf(((row[c0]     + s_bias[c0])     - mu) * rs * s_v1[c0]     + s_v2[c0],     0.f);
                    float v1 = fmaxf(((row[c0 + 1] + s_bias[c0 + 1]) - mu) * rs * s_v1[c0 + 1] + s_v2[c0 + 1], 0.f);
                    __nv_bfloat16 h0 = __float2bfloat16(v0), h1 = __float2bfloat16(v1);
                    hp[p] = (uint32_t)__bfloat16_as_ushort(h0) | ((uint32_t)__bfloat16_as_ushort(h1) << 16);
                    lp[p] = pack2(v0 - __bfloat162float(h0), v1 - __bfloat162float(h1));
                }
                *(uint4*)(oH + k0) = make_uint4(hp[0], hp[1], hp[2], hp[3]);
                *(uint4*)(oL + k0) = make_uint4(lp[0], lp[1], lp[2], lp[3]);
            }
        } else if (EPI == 1) {
            float score = 0.f;
#pragma unroll 1
            for (int k0 = 0; k0 < 64; k0 += 8) {
                uint32_t hp[4], lp[4];
#pragma unroll
                for (int p = 0; p < 4; p++) {
                    int c0 = cb + k0 + 2 * p;
                    float v0 = row[c0]     + s_bias[c0];
                    float v1 = row[c0 + 1] + s_bias[c0 + 1];
                    score += v0 * s_v1[c0] + v1 * s_v1[c0 + 1];
                    __nv_bfloat16 h0 = __float2bfloat16(v0), h1 = __float2bfloat16(v1);
                    hp[p] = (uint32_t)__bfloat16_as_ushort(h0) | ((uint32_t)__bfloat16_as_ushort(h1) << 16);
                    lp[p] = pack2(v0 - __bfloat162float(h0), v1 - __bfloat162float(h1));
                }
                *(uint4*)(oH + k0) = make_uint4(hp[0], hp[1], hp[2], hp[3]);
                *(uint4*)(oL + k0) = make_uint4(lp[0], lp[1], lp[2], lp[3]);
            }
            score += __shfl_xor_sync(0xffffffffu, score, 1);
            score += __shfl_xor_sync(0xffffffffu, score, 2);
            if (quarter == 0) g_score[grow] = score + aux2[0];
        } else if (EPI == 2) {
#pragma unroll 1
            for (int k0 = 0; k0 < 64; k0 += 8) {
                uint32_t hp[4], lp[4];
#pragma unroll
                for (int p = 0; p < 4; p++) {
                    int c0 = cb + k0 + 2 * p;
                    float v0 = fmaxf(row[c0]     + s_bias[c0],     0.f);
                    float v1 = fmaxf(row[c0 + 1] + s_bias[c0 + 1], 0.f);
                    __nv_bfloat16 h0 = __float2bfloat16(v0), h1 = __float2bfloat16(v1);
                    hp[p] = (uint32_t)__bfloat16_as_ushort(h0) | ((uint32_t)__bfloat16_as_ushort(h1) << 16);
                    lp[p] = pack2(v0 - __bfloat162float(h0), v1 - __bfloat162float(h1));
                }
                *(uint4*)(oH + k0) = make_uint4(hp[0], hp[1], hp[2], hp[3]);
                *(uint4*)(oL + k0) = make_uint4(lp[0], lp[1], lp[2], lp[3]);
            }
        } else {   // EPI 3: relu + fused delta
            float p0 = 0.f, p1 = 0.f, p2 = 0.f, p3 = 0.f;
#pragma unroll 4
            for (int k = 0; k < 64; k++) {
                int c0 = cb + k;
                float v = fmaxf(row[c0] + s_bias[c0], 0.f);
                const float* w3 = &s_wb3[c0 * 4];
                p0 += v * w3[0]; p1 += v * w3[1];
                p2 += v * w3[2]; p3 += v * w3[3];
            }
            p0 += __shfl_xor_sync(0xffffffffu, p0, 1);
            p0 += __shfl_xor_sync(0xffffffffu, p0, 2);
            p1 += __shfl_xor_sync(0xffffffffu, p1, 1);
            p1 += __shfl_xor_sync(0xffffffffu, p1, 2);
            p2 += __shfl_xor_sync(0xffffffffu, p2, 1);
            p2 += __shfl_xor_sync(0xffffffffu, p2, 2);
            p3 += __shfl_xor_sync(0xffffffffu, p3, 1);
            p3 += __shfl_xor_sync(0xffffffffu, p3, 2);
            if (quarter == 0) {
                g_delta[(long)grow * 4 + 0] = p0 + aux2[0];
                g_delta[(long)grow * 4 + 1] = p1 + aux2[1];
                g_delta[(long)grow * 4 + 2] = p2 + aux2[2];
                g_delta[(long)grow * 4 + 3] = p3 + aux2[3];
            }
        }
    }
}

// ---------------------------------------------------------------------------
// k_finalize: scatter candidate results to output (zeros prefilled)
// ---------------------------------------------------------------------------
__global__ void k_finalize(const float* __restrict__ boxes,
                           float* __restrict__ out, int out_size)
{
    int cnt = g_cnt;
    int stride = gridDim.x * blockDim.x;
    for (int i = blockIdx.x * blockDim.x + threadIdx.x; i < cnt; i += stride) {
        int v = g_idx[i];
        int q = v & 0xFFFF;
        unsigned cm = (unsigned)(v >> 16);
        float4 bx = *(const float4*)(boxes + (long)q * 4);
        float cx = bx.x, cy = bx.y, w = bx.z, h = bx.w;
        float ny = cy + 0.5f * h, nw = w * 0.8f, nh = h * 0.8f;
        float dd[4];
        dd[0] = g_delta[(long)i * 4 + 0]; dd[1] = g_delta[(long)i * 4 + 1];
        dd[2] = g_delta[(long)i * 4 + 2]; dd[3] = g_delta[(long)i * 4 + 3];
        float sc = g_score[i];
        float lb[4]  = {cx,            ny, nw, nh};
        float rbx[4] = {cx + 0.1f * w, ny, nw, nh};
#pragma unroll
        for (int s = 0; s < 2; s++) {
            if (!((cm >> s) & 1u)) continue;
            const float* cb = s ? rbx : lb;
            long basei = ((long)q * 2 + s) * 5;
#pragma unroll
            for (int c = 0; c < 4; c++) {
                float x = fminf(fmaxf(cb[c], 0.f), 1.f);
                float inv = logf(fmaxf(x, 1e-5f) / fmaxf(1.f - x, 1e-5f));
                float t = dd[c] + inv;
                out[basei + c] = 1.f / (1.f + expf(-t));
            }
            out[basei + 4] = sc;
            if (out_size >= BQ * 10 + BQ * 2)
                out[BQ * 10 + (long)q * 2 + s] = 1.f;
        }
    }
}

// ---------------------------------------------------------------------------
// Launch. Launch #6 = GEMM-2 (ncu -s 5 -c 1 profiles it).
// ---------------------------------------------------------------------------
extern "C" void kernel_launch(void* const* d_in, const int* in_sizes, int n_in,
                              void* d_out, int out_size)
{
    const float* logits   = (const float*)d_in[0];
    const float* boxes    = (const float*)d_in[1];
    const float* features = (const float*)d_in[2];
    const float* W_p1 = (const float*)d_in[4];
    const float* b_p1 = (const float*)d_in[5];
    const float* ln_g = (const float*)d_in[6];
    const float* ln_b = (const float*)d_in[7];
    const float* W_p2 = (const float*)d_in[8];
    const float* b_p2 = (const float*)d_in[9];
    const float* W_b1 = (const float*)d_in[10];
    const float* b_b1 = (const float*)d_in[11];
    const float* W_b2 = (const float*)d_in[12];
    const float* b_b2 = (const float*)d_in[13];
    const float* W_b3 = (const float*)d_in[14];
    const float* b_b3 = (const float*)d_in[15];
    const float* W_s  = (const float*)d_in[16];
    const float* b_s  = (const float*)d_in[17];
    float* out = (float*)d_out;
    (void)in_sizes; (void)n_in;

    cudaFuncSetAttribute(k_mmagemm<0>, cudaFuncAttributeMaxDynamicSharedMemorySize, SMEM_REQ);
    cudaFuncSetAttribute(k_mmagemm<1>, cudaFuncAttributeMaxDynamicSharedMemorySize, SMEM_REQ);
    cudaFuncSetAttribute(k_mmagemm<2>, cudaFuncAttributeMaxDynamicSharedMemorySize, SMEM_REQ);
    cudaFuncSetAttribute(k_mmagemm<3>, cudaFuncAttributeMaxDynamicSharedMemorySize, SMEM_REQ);

    k_zero<<<750, 256>>>(out, out_size);                               // 1
    k_convw<<<1024, 256>>>(W_p1, W_p2, W_b1, W_b2);                    // 2
    k_mask<<<B_ * 2, 1024>>>(logits, boxes);                           // 3
    k_featgather<<<1000, 256>>>(features);                             // 4

    // G1: hdd = relu(LN(feat@W_p1+b)) : planes0 -> planes1            // 5
    k_mmagemm<0><<<1000, 256, SMEM_REQ>>>(0, 1, 0, b_p1, ln_g, ln_b);
    // G2: ary = planes1@W_p2+b (raw) + score : planes1 -> planes0     // 6 (ncu)
    k_mmagemm<1><<<1000, 256, SMEM_REQ>>>(1, 0, 1, b_p2, W_s, b_s);
    // G3: m1 = relu(planes0@W_b1+b) : planes0 -> planes1
    k_mmagemm<2><<<1000, 256, SMEM_REQ>>>(0, 1, 2, b_b1, b_b1, b_b1);
    // G4: delta = relu(planes1@W_b2+b)@W_b3 + b_b3
    k_mmagemm<3><<<1000, 256, SMEM_REQ>>>(1, 0, 3, b_b2, W_b3, b_b3);

    k_finalize<<<250, 256>>>(boxes, out, out_size);
}

// round 12
// speedup vs baseline: 9.5818x; 1.4159x over previous
#include <cuda_runtime.h>
#include <cuda_bf16.h>
#include <math.h>
#include <stdint.h>

#define B_  64
#define Q_  1000
#define BQ  64000
#define D_  256
#define LOGIT_THR 0.8472978603872034f   // sigmoid(x)>0.7  <=>  x>ln(7/3)

// ---------------------------------------------------------------------------
// Device-global scratch
// ---------------------------------------------------------------------------
__device__ __nv_bfloat16 g_wHp[4][D_ * D_];   // transposed weights [n][k], hi plane
__device__ __nv_bfloat16 g_wLp[4][D_ * D_];   // lo plane
__device__ int           g_idx[BQ];           // q | (cand_bits<<16)
__device__ int           g_cnt;

// ---------------------------------------------------------------------------
// PTX helpers (plain-sm_100 legal)
// ---------------------------------------------------------------------------
__device__ __forceinline__ uint32_t smem_u32(const void* p) {
    uint32_t r;
    asm("{ .reg .u64 t; cvta.to.shared.u64 t, %1; cvt.u32.u64 %0, t; }" : "=r"(r) : "l"(p));
    return r;
}
__device__ __forceinline__ void cp16(uint32_t dst, const void* src) {
    asm volatile("cp.async.cg.shared.global [%0], [%1], 16;" :: "r"(dst), "l"(src));
}
#define CP_COMMIT()  asm volatile("cp.async.commit_group;")
#define CP_WAIT0()   asm volatile("cp.async.wait_group 0;")

#define LDSM4(r, addr) \
    asm volatile("ldmatrix.sync.aligned.m8n8.x4.shared.b16 {%0,%1,%2,%3}, [%4];" \
        : "=r"((r)[0]), "=r"((r)[1]), "=r"((r)[2]), "=r"((r)[3]) : "r"(addr))

#define MMA(d, a, b0, b1) \
    asm volatile("mma.sync.aligned.m16n8k16.row.col.f32.bf16.bf16.f32 " \
        "{%0,%1,%2,%3},{%4,%5,%6,%7},{%8,%9},{%0,%1,%2,%3};" \
        : "+f"((d)[0]), "+f"((d)[1]), "+f"((d)[2]), "+f"((d)[3]) \
        : "r"((a)[0]), "r"((a)[1]), "r"((a)[2]), "r"((a)[3]), "r"(b0), "r"(b1))

__device__ __forceinline__ uint32_t pack2(float a, float b) {
    return (uint32_t)__bfloat16_as_ushort(__float2bfloat16(a))
         | ((uint32_t)__bfloat16_as_ushort(__float2bfloat16(b)) << 16);
}
// split pair -> hi word, lo word
__device__ __forceinline__ void split2(float a, float b, uint32_t& hw, uint32_t& lw) {
    __nv_bfloat16 h0 = __float2bfloat16(a), h1 = __float2bfloat16(b);
    hw = (uint32_t)__bfloat16_as_ushort(h0) | ((uint32_t)__bfloat16_as_ushort(h1) << 16);
    lw = pack2(a - __bfloat162float(h0), b - __bfloat162float(h1));
}

// ---------------------------------------------------------------------------
// k_zero / k_convw / k_mask (k_mask unchanged from R11)
// ---------------------------------------------------------------------------
__global__ void k_zero(float* __restrict__ out, int out_size)
{
    int i = blockIdx.x * blockDim.x + threadIdx.x;
    if (i == 0) g_cnt = 0;
    int zn4 = ((out_size >= BQ * 10 + BQ * 2) ? (BQ * 10 + BQ * 2) : (BQ * 10)) / 4;
    float4 z = make_float4(0.f, 0.f, 0.f, 0.f);
    float4* o4 = (float4*)out;
    for (int j = i; j < zn4; j += gridDim.x * blockDim.x) o4[j] = z;
}

__global__ void k_convw(const float* __restrict__ W0, const float* __restrict__ W1,
                        const float* __restrict__ W2, const float* __restrict__ W3)
{
    int wSel = blockIdx.x >> 8;
    int idx = (blockIdx.x & 255) * 256 + threadIdx.x;
    const float* W = (wSel == 0) ? W0 : (wSel == 1) ? W1 : (wSel == 2) ? W2 : W3;
    int k = idx >> 8, n = idx & 255;
    float x = W[idx];
    __nv_bfloat16 h = __float2bfloat16(x);
    g_wHp[wSel][n * D_ + k] = h;
    g_wLp[wSel][n * D_ + k] = __float2bfloat16(x - __bfloat162float(h));
}

__global__ void __launch_bounds__(1024) k_mask(const float* __restrict__ logits,
                                               const float* __restrict__ boxes)
{
    __shared__ float tx1[Q_], ty1[Q_], tx2[Q_], ty2[Q_], tar[Q_];
    __shared__ unsigned char tfl[Q_];
    __shared__ int s_fq[512];
    __shared__ int tn, fn;

    int b = blockIdx.x >> 1, slice = blockIdx.x & 1;
    int t = threadIdx.x;
    if (t == 0) { tn = 0; fn = 0; }
    __syncthreads();

    if (t < Q_) {
        const float* l = logits + ((long)b * Q_ + t) * 6;
        unsigned f = 0;
        if (l[0] > LOGIT_THR) f |= 1u;
        if (l[4] > LOGIT_THR) f |= 2u;
        if (l[1] > LOGIT_THR) f |= 4u;
        if (l[5] > LOGIT_THR) f |= 8u;
        if (f) {
            const float* bx = boxes + ((long)b * Q_ + t) * 4;
            float cx = bx[0], cy = bx[1], w = bx[2], h = bx[3];
            if (f & 0xCu) {
                int p = atomicAdd(&tn, 1);
                tx1[p] = cx - 0.5f * w; ty1[p] = cy - 0.5f * h;
                tx2[p] = cx + 0.5f * w; ty2[p] = cy + 0.5f * h;
                tar[p] = w * h;
                tfl[p] = (unsigned char)((f >> 2) & 3u);
            }
            if ((f & 3u) && ((t >> 9) == slice)) {
                int p = atomicAdd(&fn, 1);
                s_fq[p] = t | (int)((f & 3u) << 16);
            }
        }
    }
    __syncthreads();

    int nt = tn, nf = fn;
    int sub = t & 3;

    for (int e = t >> 2; e < nf; e += 256) {
        int v = s_fq[e];
        int q = v & 0xFFFF;
        unsigned need = (unsigned)(v >> 16) & 3u;
        const float4 bx = *(const float4*)(boxes + ((long)b * Q_ + q) * 4);
        float x1 = bx.x - 0.5f * bx.z, y1 = bx.y - 0.5f * bx.w;
        float x2 = bx.x + 0.5f * bx.z, y2 = bx.y + 0.5f * bx.w;
        float ar = bx.z * bx.w;
        unsigned has = 0;
        for (int j = sub; j < nt; j += 4) {
            float xl = fmaxf(x1, tx1[j]), yt = fmaxf(y1, ty1[j]);
            float xr = fminf(x2, tx2[j]), yb = fminf(y2, ty2[j]);
            float inter = fmaxf(xr - xl, 0.f) * fmaxf(yb - yt, 0.f);
            float uni = ar + tar[j] - inter;
            if (inter > 0.5f * uni) {
                has |= (unsigned)tfl[j];
                if ((has & need) == need) break;
            }
        }
        has |= __shfl_xor_sync(0xffffffffu, has, 1);
        has |= __shfl_xor_sync(0xffffffffu, has, 2);
        if (sub == 0) {
            unsigned cm = need & ~has;
            if (cm) {
                int pos = atomicAdd(&g_cnt, 1);
                g_idx[pos] = (b * Q_ + q) | ((int)cm << 16);
            }
        }
    }
}

// ---------------------------------------------------------------------------
// k_fused: gather + 4 chained split-bf16 GEMMs + finalize, all per-CTA.
//   CTA = 64 compacted rows. ACT persistent in smem (hi/lo planes, 4 K-blocks
//   of 64 rows x 64 cols, 128B rows, SW128 swizzle). B streamed one plane at
//   a time through a 32KB buffer. Epilogues fully register-resident.
// smem map (bytes):
//   ACT_H 0..32768 (4 blocks x 8KB) | ACT_L 32768..65536
//   B     65536..98304 (32KB)
//   BIAS  98304 (1KB) | V1 99328 (4KB: lng|ws|wb3) | V2 103424 (1KB: lnb)
//   PS    104448 (1KB) | PS2 105472 (1KB) | DP(=PS overlay) 104448..108544
//   SCORE 108544 (256B) | QIDX 108800 (256B)   => total 109056 (occ 2)
// ---------------------------------------------------------------------------
#define S_ACTH 0
#define S_ACTL 32768
#define S_B    65536
#define S_BIAS 98304
#define S_V1   99328
#define S_V2   103424
#define S_PS   104448
#define S_PS2  105472
#define S_DP   104448
#define S_SC   108544
#define S_QI   108800
#define FUSED_SMEM 109056

__global__ void __launch_bounds__(256, 2) k_fused(
    const float* __restrict__ feat, const float* __restrict__ boxes,
    const float* __restrict__ b1, const float* __restrict__ lng, const float* __restrict__ lnb,
    const float* __restrict__ b2, const float* __restrict__ ws, const float* __restrict__ bs,
    const float* __restrict__ b3, const float* __restrict__ b4,
    const float* __restrict__ wb3, const float* __restrict__ bb3,
    float* __restrict__ out, int out_size)
{
    int cnt = g_cnt;
    int blockRow = blockIdx.x * 64;
    if (blockRow >= cnt) return;

    extern __shared__ __align__(1024) char sm[];
    uint32_t base = smem_u32(sm);
    int tid = threadIdx.x, wid = tid >> 5, lane = tid & 31;
    int wm = wid & 1, wn = wid >> 1;          // warp tile 32M x 64N
    int qg = lane >> 2, qt = lane & 3;        // quad row-group / col-sub

    // ---------------- prologue: qidx + gather features into ACT ----------------
    if (tid < 64) {
        int gr = blockRow + tid;
        ((int*)(sm + S_QI))[tid] = (gr < cnt) ? g_idx[gr] : -1;
    }
    for (int it = tid; it < 2048; it += 256) {       // 64 rows x 32 groups of 8 cols
        int row = it >> 5, grp = it & 31;
        uint4 hi = make_uint4(0, 0, 0, 0), lo = make_uint4(0, 0, 0, 0);
        int gr = blockRow + row;
        if (gr < cnt) {
            int q = g_idx[gr] & 0xFFFF;
            const float4* f4 = (const float4*)feat + (size_t)q * 64 + grp * 2;
            float4 fa = __ldg(f4), fb = __ldg(f4 + 1);
            split2(fa.x, fa.y, hi.x, lo.x);
            split2(fa.z, fa.w, hi.y, lo.y);
            split2(fb.x, fb.y, hi.z, lo.z);
            split2(fb.z, fb.w, hi.w, lo.w);
        }
        int c8 = grp * 8;
        int blk = c8 >> 6;
        uint32_t sw = blk * 8192 + row * 128 + (((c8 & 63) * 2) ^ ((row & 7) << 4));
        *(uint4*)(sm + S_ACTH + sw) = hi;
        *(uint4*)(sm + S_ACTL + sw) = lo;
    }
    __syncthreads();

    float* s_bias = (float*)(sm + S_BIAS);
    float* s_v1   = (float*)(sm + S_V1);
    float* s_v2   = (float*)(sm + S_V2);
    float* s_ps   = (float*)(sm + S_PS);
    float* s_ps2  = (float*)(sm + S_PS2);
    float* s_dp   = (float*)(sm + S_DP);
    float* s_sc   = (float*)(sm + S_SC);

    // ---------------- layer loop ----------------
#pragma unroll 1
    for (int L = 0; L < 4; L++) {
        const float* bias = (L == 0) ? b1 : (L == 1) ? b2 : (L == 2) ? b3 : b4;
        const __nv_bfloat16* wH = g_wHp[L];
        const __nv_bfloat16* wL = g_wLp[L];

        s_bias[tid] = __ldg(bias + tid);
        if (L == 0) { s_v1[tid] = __ldg(lng + tid); s_v2[tid] = __ldg(lnb + tid); }
        if (L == 1) { s_v1[tid] = __ldg(ws + tid); }
        if (L == 3) { ((float4*)s_v1)[tid] = __ldg((const float4*)wb3 + tid); }
        __syncthreads();

        float acc[2][8][4];
#pragma unroll
        for (int i = 0; i < 2; i++)
#pragma unroll
            for (int j = 0; j < 8; j++)
#pragma unroll
                for (int r = 0; r < 4; r++) acc[i][j][r] = 0.f;

#pragma unroll 1
        for (int c = 0; c < 4; c++) {
            // ---- B hi plane ----
#pragma unroll 1
            for (int s = tid; s < 2048; s += 256) {
                int n = s >> 3, seg = s & 7;
                uint32_t dst = base + S_B + n * 128 + ((seg * 16) ^ ((n & 7) << 4));
                cp16(dst, wH + (size_t)n * D_ + c * 64 + seg * 8);
            }
            CP_COMMIT(); CP_WAIT0();
            __syncthreads();
#pragma unroll
            for (int ks = 0; ks < 4; ks++) {
                int colb = ((lane >> 4) << 4) | (ks << 5);
                int rl = lane & 15;
                uint32_t Af[2][4], Bf[4][4];
#pragma unroll
                for (int j4 = 0; j4 < 4; j4++) {
                    int n = wn * 64 + j4 * 16 + rl;
                    LDSM4(Bf[j4], base + S_B + n * 128 + (colb ^ ((n & 7) << 4)));
                }
#pragma unroll
                for (int i = 0; i < 2; i++) {             // A-hi x B-hi
                    int row = wm * 32 + i * 16 + rl;
                    LDSM4(Af[i], base + S_ACTH + c * 8192 + row * 128 + (colb ^ ((row & 7) << 4)));
                }
#pragma unroll
                for (int i = 0; i < 2; i++)
#pragma unroll
                    for (int j = 0; j < 8; j++) {
                        int j4 = j >> 1, sel = j & 1;
                        MMA(acc[i][j], Af[i], Bf[j4][sel], Bf[j4][sel + 2]);
                    }
#pragma unroll
                for (int i = 0; i < 2; i++) {             // A-lo x B-hi
                    int row = wm * 32 + i * 16 + rl;
                    LDSM4(Af[i], base + S_ACTL + c * 8192 + row * 128 + (colb ^ ((row & 7) << 4)));
                }
#pragma unroll
                for (int i = 0; i < 2; i++)
#pragma unroll
                    for (int j = 0; j < 8; j++) {
                        int j4 = j >> 1, sel = j & 1;
                        MMA(acc[i][j], Af[i], Bf[j4][sel], Bf[j4][sel + 2]);
                    }
            }
            __syncthreads();
            // ---- B lo plane ----
#pragma unroll 1
            for (int s = tid; s < 2048; s += 256) {
                int n = s >> 3, seg = s & 7;
                uint32_t dst = base + S_B + n * 128 + ((seg * 16) ^ ((n & 7) << 4));
                cp16(dst, wL + (size_t)n * D_ + c * 64 + seg * 8);
            }
            CP_COMMIT(); CP_WAIT0();
            __syncthreads();
#pragma unroll
            for (int ks = 0; ks < 4; ks++) {
                int colb = ((lane >> 4) << 4) | (ks << 5);
                int rl = lane & 15;
                uint32_t Af[2][4], Bf[4][4];
#pragma unroll
                for (int j4 = 0; j4 < 4; j4++) {
                    int n = wn * 64 + j4 * 16 + rl;
                    LDSM4(Bf[j4], base + S_B + n * 128 + (colb ^ ((n & 7) << 4)));
                }
#pragma unroll
                for (int i = 0; i < 2; i++) {             // A-hi x B-lo
                    int row = wm * 32 + i * 16 + rl;
                    LDSM4(Af[i], base + S_ACTH + c * 8192 + row * 128 + (colb ^ ((row & 7) << 4)));
                }
#pragma unroll
                for (int i = 0; i < 2; i++)
#pragma unroll
                    for (int j = 0; j < 8; j++) {
                        int j4 = j >> 1, sel = j & 1;
                        MMA(acc[i][j], Af[i], Bf[j4][sel], Bf[j4][sel + 2]);
                    }
            }
            __syncthreads();
        }

        // ---------------- epilogue (register-resident) ----------------
        // thread owns rows r(i,h) = wm*32 + i*16 + qg + h*8, cols c(j) = wn*64 + j*8 + 2*qt (+1)
        if (L == 0) {
            // stats
            float ps[2][2] = {{0,0},{0,0}}, ps2[2][2] = {{0,0},{0,0}};
#pragma unroll
            for (int i = 0; i < 2; i++)
#pragma unroll
                for (int j = 0; j < 8; j++) {
                    int c0 = wn * 64 + j * 8 + 2 * qt;
                    float v00 = acc[i][j][0] + s_bias[c0], v01 = acc[i][j][1] + s_bias[c0 + 1];
                    float v10 = acc[i][j][2] + s_bias[c0], v11 = acc[i][j][3] + s_bias[c0 + 1];
                    ps[i][0] += v00 + v01; ps2[i][0] += v00 * v00 + v01 * v01;
                    ps[i][1] += v10 + v11; ps2[i][1] += v10 * v10 + v11 * v11;
                }
#pragma unroll
            for (int i = 0; i < 2; i++)
#pragma unroll
                for (int h = 0; h < 2; h++) {
                    ps[i][h]  += __shfl_xor_sync(0xffffffffu, ps[i][h], 1);
                    ps[i][h]  += __shfl_xor_sync(0xffffffffu, ps[i][h], 2);
                    ps2[i][h] += __shfl_xor_sync(0xffffffffu, ps2[i][h], 1);
                    ps2[i][h] += __shfl_xor_sync(0xffffffffu, ps2[i][h], 2);
                    if (qt == 0) {
                        int r = wm * 32 + i * 16 + qg + h * 8;
                        s_ps[r * 4 + wn] = ps[i][h];
                        s_ps2[r * 4 + wn] = ps2[i][h];
                    }
                }
            __syncthreads();
            float mu[2][2], rs[2][2];
#pragma unroll
            for (int i = 0; i < 2; i++)
#pragma unroll
                for (int h = 0; h < 2; h++) {
                    int r = wm * 32 + i * 16 + qg + h * 8;
                    float S = s_ps[r * 4] + s_ps[r * 4 + 1] + s_ps[r * 4 + 2] + s_ps[r * 4 + 3];
                    float S2 = s_ps2[r * 4] + s_ps2[r * 4 + 1] + s_ps2[r * 4 + 2] + s_ps2[r * 4 + 3];
                    float m = S * (1.f / 256.f);
                    mu[i][h] = m;
                    rs[i][h] = rsqrtf(S2 * (1.f / 256.f) - m * m + 1e-5f);
                }
            __syncthreads();   // s_ps free for reuse; also order before ACT overwrite? ACT reads done.
#pragma unroll
            for (int i = 0; i < 2; i++)
#pragma unroll
                for (int j = 0; j < 8; j++) {
                    int c0 = wn * 64 + j * 8 + 2 * qt;
                    int byte = (c0 & 63) * 2, blk = c0 >> 6;
                    uint32_t gb = blk * 8192 + ((byte & ~15)) ;  // granule base pre-row
#pragma unroll
                    for (int h = 0; h < 2; h++) {
                        int r = wm * 32 + i * 16 + qg + h * 8;
                        float v0 = acc[i][j][2 * h]     + s_bias[c0];
                        float v1 = acc[i][j][2 * h + 1] + s_bias[c0 + 1];
                        v0 = fmaxf((v0 - mu[i][h]) * rs[i][h] * s_v1[c0]     + s_v2[c0],     0.f);
                        v1 = fmaxf((v1 - mu[i][h]) * rs[i][h] * s_v1[c0 + 1] + s_v2[c0 + 1], 0.f);
                        uint32_t hw, lw; split2(v0, v1, hw, lw);
                        uint32_t a = blk * 8192 + r * 128 + ((byte & ~15) ^ ((r & 7) << 4)) + (byte & 15);
                        *(uint32_t*)(sm + S_ACTH + a) = hw;
                        *(uint32_t*)(sm + S_ACTL + a) = lw;
                    }
                    (void)gb;
                }
        } else if (L == 1) {
            float sc[2][2] = {{0,0},{0,0}};
#pragma unroll
            for (int i = 0; i < 2; i++)
#pragma unroll
                for (int j = 0; j < 8; j++) {
                    int c0 = wn * 64 + j * 8 + 2 * qt;
                    int byte = (c0 & 63) * 2, blk = c0 >> 6;
#pragma unroll
                    for (int h = 0; h < 2; h++) {
                        int r = wm * 32 + i * 16 + qg + h * 8;
                        float v0 = acc[i][j][2 * h]     + s_bias[c0];
                        float v1 = acc[i][j][2 * h + 1] + s_bias[c0 + 1];
                        sc[i][h] += v0 * s_v1[c0] + v1 * s_v1[c0 + 1];
                        uint32_t hw, lw; split2(v0, v1, hw, lw);
                        uint32_t a = blk * 8192 + r * 128 + ((byte & ~15) ^ ((r & 7) << 4)) + (byte & 15);
                        *(uint32_t*)(sm + S_ACTH + a) = hw;
                        *(uint32_t*)(sm + S_ACTL + a) = lw;
                    }
                }
#pragma unroll
            for (int i = 0; i < 2; i++)
#pragma unroll
                for (int h = 0; h < 2; h++) {
                    sc[i][h] += __shfl_xor_sync(0xffffffffu, sc[i][h], 1);
                    sc[i][h] += __shfl_xor_sync(0xffffffffu, sc[i][h], 2);
                    if (qt == 0) {
                        int r = wm * 32 + i * 16 + qg + h * 8;
                        s_ps[r * 4 + wn] = sc[i][h];
                    }
                }
            __syncthreads();
            if (tid < 64)
                s_sc[tid] = s_ps[tid * 4] + s_ps[tid * 4 + 1] + s_ps[tid * 4 + 2] + s_ps[tid * 4 + 3]
                          + __ldg(bs);
        } else if (L == 2) {
#pragma unroll
            for (int i = 0; i < 2; i++)
#pragma unroll
                for (int j = 0; j < 8; j++) {
                    int c0 = wn * 64 + j * 8 + 2 * qt;
                    int byte = (c0 & 63) * 2, blk = c0 >> 6;
#pragma unroll
                    for (int h = 0; h < 2; h++) {
                        int r = wm * 32 + i * 16 + qg + h * 8;
                        float v0 = fmaxf(acc[i][j][2 * h]     + s_bias[c0],     0.f);
                        float v1 = fmaxf(acc[i][j][2 * h + 1] + s_bias[c0 + 1], 0.f);
                        uint32_t hw, lw; split2(v0, v1, hw, lw);
                        uint32_t a = blk * 8192 + r * 128 + ((byte & ~15) ^ ((r & 7) << 4)) + (byte & 15);
                        *(uint32_t*)(sm + S_ACTH + a) = hw;
                        *(uint32_t*)(sm + S_ACTL + a) = lw;
                    }
                }
        } else {
            // L == 3: relu + delta dots; s_v1 holds W_b3 [256][4]
#pragma unroll
            for (int i = 0; i < 2; i++) {
                float dp[2][4] = {{0,0,0,0},{0,0,0,0}};
#pragma unroll
                for (int j = 0; j < 8; j++) {
                    int c0 = wn * 64 + j * 8 + 2 * qt;
#pragma unroll
                    for (int h = 0; h < 2; h++) {
                        float v0 = fmaxf(acc[i][j][2 * h]     + s_bias[c0],     0.f);
                        float v1 = fmaxf(acc[i][j][2 * h + 1] + s_bias[c0 + 1], 0.f);
                        const float* w0 = &s_v1[c0 * 4];
#pragma unroll
                        for (int k = 0; k < 4; k++)
                            dp[h][k] += v0 * w0[k] + v1 * w0[4 + k];
                    }
                }
#pragma unroll
                for (int h = 0; h < 2; h++)
#pragma unroll
                    for (int k = 0; k < 4; k++) {
                        dp[h][k] += __shfl_xor_sync(0xffffffffu, dp[h][k], 1);
                        dp[h][k] += __shfl_xor_sync(0xffffffffu, dp[h][k], 2);
                        if (qt == 0) {
                            int r = wm * 32 + i * 16 + qg + h * 8;
                            s_dp[r * 16 + wn * 4 + k] = dp[h][k];
                        }
                    }
            }
            __syncthreads();
            // finalize per row
            if (tid < 64) {
                int v = ((int*)(sm + S_QI))[tid];
                if (v >= 0) {
                    float d[4];
#pragma unroll
                    for (int k = 0; k < 4; k++)
                        d[k] = s_dp[tid * 16 + k] + s_dp[tid * 16 + 4 + k]
                             + s_dp[tid * 16 + 8 + k] + s_dp[tid * 16 + 12 + k]
                             + __ldg(bb3 + k);
                    float scv = s_sc[tid];
                    int q = v & 0xFFFF;
                    unsigned cm = (unsigned)(v >> 16);
                    float4 bx = *(const float4*)(boxes + (long)q * 4);
                    float cx = bx.x, cy = bx.y, w = bx.z, hh = bx.w;
                    float ny = cy + 0.5f * hh, nw = w * 0.8f, nh = hh * 0.8f;
                    float lb[4]  = {cx,            ny, nw, nh};
                    float rbx[4] = {cx + 0.1f * w, ny, nw, nh};
#pragma unroll
                    for (int s = 0; s < 2; s++) {
                        if (!((cm >> s) & 1u)) continue;
                        const float* cb = s ? rbx : lb;
                        long basei = ((long)q * 2 + s) * 5;
#pragma unroll
                        for (int c = 0; c < 4; c++) {
                            float x = fminf(fmaxf(cb[c], 0.f), 1.f);
                            float inv = logf(fmaxf(x, 1e-5f) / fmaxf(1.f - x, 1e-5f));
                            out[basei + c] = 1.f / (1.f + expf(-(d[c] + inv)));
                        }
                        out[basei + 4] = scv;
                        if (out_size >= BQ * 10 + BQ * 2)
                            out[BQ * 10 + (long)q * 2 + s] = 1.f;
                    }
                }
            }
        }
        __syncthreads();   // ACT/score writes visible before next layer
    }
}

// ---------------------------------------------------------------------------
// Launch: 4 kernels total
// ---------------------------------------------------------------------------
extern "C" void kernel_launch(void* const* d_in, const int* in_sizes, int n_in,
                              void* d_out, int out_size)
{
    const float* logits   = (const float*)d_in[0];
    const float* boxes    = (const float*)d_in[1];
    const float* features = (const float*)d_in[2];
    const float* W_p1 = (const float*)d_in[4];
    const float* b_p1 = (const float*)d_in[5];
    const float* ln_g = (const float*)d_in[6];
    const float* ln_b = (const float*)d_in[7];
    const float* W_p2 = (const float*)d_in[8];
    const float* b_p2 = (const float*)d_in[9];
    const float* W_b1 = (const float*)d_in[10];
    const float* b_b1 = (const float*)d_in[11];
    const float* W_b2 = (const float*)d_in[12];
    const float* b_b2 = (const float*)d_in[13];
    const float* W_b3 = (const float*)d_in[14];
    const float* b_b3 = (const float*)d_in[15];
    const float* W_s  = (const float*)d_in[16];
    const float* b_s  = (const float*)d_in[17];
    float* out = (float*)d_out;
    (void)in_sizes; (void)n_in;

    cudaFuncSetAttribute(k_fused, cudaFuncAttributeMaxDynamicSharedMemorySize, FUSED_SMEM);

    k_zero<<<750, 256>>>(out, out_size);
    k_convw<<<1024, 256>>>(W_p1, W_p2, W_b1, W_b2);
    k_mask<<<B_ * 2, 1024>>>(logits, boxes);
    k_fused<<<1000, 256, FUSED_SMEM>>>(features, boxes,
                                       b_p1, ln_g, ln_b,
                                       b_p2, W_s, b_s,
                                       b_b1, b_b2,
                                       W_b3, b_b3,
                                       out, out_size);
}